// round 1
// baseline (speedup 1.0000x reference)
#include <cuda_runtime.h>
#include <cuda_bf16.h>
#include <math.h>

#define B_  4
#define S_  2048
#define D_  512
#define H_  8
#define DH_ 64
#define F_  2048
#define NL_ 4
#define BS_ (B_*S_)          // 8192 rows
#define EPS_    1e-6f
#define LN_EPS_ 1e-5f

// ---------------- scratch (device globals; no allocation allowed) ----------------
__device__ float g_h   [BS_*D_];
__device__ float g_q   [BS_*D_];
__device__ float g_k   [BS_*D_];
__device__ float g_v   [BS_*D_];
__device__ float g_attn[BS_*D_];
__device__ float g_tmp [BS_*D_];
__device__ float g_ffn [BS_*F_];
__device__ int   g_len [B_];

// ---------------- lengths: count of nonzero tokens per batch ----------------
__global__ void lengths_kernel(const int* __restrict__ x) {
    int b = blockIdx.x;
    int tid = threadIdx.x;
    __shared__ int sred[256];
    int cnt = 0;
    for (int s = tid; s < S_; s += 256) cnt += (x[b * S_ + s] != 0) ? 1 : 0;
    sred[tid] = cnt;
    __syncthreads();
    for (int o = 128; o > 0; o >>= 1) {
        if (tid < o) sred[tid] += sred[tid + o];
        __syncthreads();
    }
    if (tid == 0) g_len[b] = sred[0];
}

// ---------------- embedding + positional encoding ----------------
__global__ void embed_kernel(const int* __restrict__ x,
                             const float* __restrict__ emb,
                             const float* __restrict__ pe) {
    int row = blockIdx.x;                 // 0..BS_-1
    int s = row % S_;
    int tok = x[row];
    const float4* e4 = (const float4*)(emb + (size_t)tok * D_);
    const float4* p4 = (const float4*)(pe + (size_t)s * D_);
    float4* h4 = (float4*)(g_h + (size_t)row * D_);
    int i = threadIdx.x;                  // 128 threads, D_/4 = 128
    float4 a = e4[i], p = p4[i];
    h4[i] = make_float4(a.x + p.x, a.y + p.y, a.z + p.z, a.w + p.w);
}

// ---------------- SGEMM: C[M,N] = A[M,K] @ W[K,N] + bias, optional relu ----------------
// 128x128 tile, BK=8, 256 threads, 8x8 per thread.
#define BM 128
#define BN 128
#define BK 8

__global__ __launch_bounds__(256, 2)
void sgemm_kernel(const float* __restrict__ A, const float* __restrict__ Bm,
                  const float* __restrict__ bias, float* __restrict__ C,
                  int M, int N, int K, int relu) {
    __shared__ float As[BK][BM];
    __shared__ float Bs[BK][BN];

    int bx = blockIdx.x;   // N tile
    int by = blockIdx.y;   // M tile
    int tid = threadIdx.x;

    // A tile loader: 128 rows x 8 cols; thread loads one float4
    int arow = tid >> 1;
    int acol = (tid & 1) * 4;
    // B tile loader: 8 rows x 128 cols; thread loads one float4
    int brow = tid >> 5;
    int bcol = (tid & 31) * 4;

    const float* Aptr = A + ((size_t)(by * BM + arow)) * K + acol;
    const float* Bptr = Bm + (size_t)brow * N + bx * BN + bcol;

    int tx = tid & 15;
    int ty = tid >> 4;

    float acc[8][8];
#pragma unroll
    for (int i = 0; i < 8; i++)
#pragma unroll
        for (int j = 0; j < 8; j++) acc[i][j] = 0.f;

    for (int k0 = 0; k0 < K; k0 += BK) {
        float4 a4 = *(const float4*)Aptr;  Aptr += BK;
        float4 b4 = *(const float4*)Bptr;  Bptr += (size_t)BK * N;

        As[acol + 0][arow] = a4.x;
        As[acol + 1][arow] = a4.y;
        As[acol + 2][arow] = a4.z;
        As[acol + 3][arow] = a4.w;
        *(float4*)&Bs[brow][bcol] = b4;
        __syncthreads();

#pragma unroll
        for (int kk = 0; kk < BK; kk++) {
            float ar[8], br[8];
            *(float4*)(ar)     = *(const float4*)&As[kk][ty * 8];
            *(float4*)(ar + 4) = *(const float4*)&As[kk][ty * 8 + 4];
            *(float4*)(br)     = *(const float4*)&Bs[kk][tx * 8];
            *(float4*)(br + 4) = *(const float4*)&Bs[kk][tx * 8 + 4];
#pragma unroll
            for (int i = 0; i < 8; i++)
#pragma unroll
                for (int j = 0; j < 8; j++)
                    acc[i][j] = fmaf(ar[i], br[j], acc[i][j]);
        }
        __syncthreads();
    }

    int crow = by * BM + ty * 8;
    int ccol = bx * BN + tx * 8;
    float bv[8];
#pragma unroll
    for (int j = 0; j < 8; j++) bv[j] = bias[ccol + j];

#pragma unroll
    for (int i = 0; i < 8; i++) {
        float* cp = C + (size_t)(crow + i) * N + ccol;
        float o[8];
#pragma unroll
        for (int j = 0; j < 8; j++) {
            float vv = acc[i][j] + bv[j];
            if (relu) vv = fmaxf(vv, 0.f);
            o[j] = vv;
        }
        *(float4*)(cp)     = *(float4*)(o);
        *(float4*)(cp + 4) = *(float4*)(o + 4);
    }
}

// ---------------- causal linear attention ----------------
// grid: (B_*H_, 4) ; block 256 threads.
// blockIdx.y picks 16 of the 64 output dims (state columns are independent).
// Thread (e_local, j): owns state S[d in j*4..j*4+3][e], plus replicated cumK slice.
#define CH 16
__global__ __launch_bounds__(256)
void attn_kernel(const float* __restrict__ q, const float* __restrict__ k,
                 const float* __restrict__ v, float* __restrict__ out) {
    int bh = blockIdx.x;
    int b = bh / H_, h = bh % H_;
    int tid = threadIdx.x;
    int e = blockIdx.y * 16 + (tid >> 4);   // 0..63 within head
    int j = tid & 15;
    int d0 = j * 4;
    int len = g_len[b];

    __shared__ float qs[CH][DH_], ks[CH][DH_], vs[CH][DH_];

    float Sst[4] = {0.f, 0.f, 0.f, 0.f};
    float cK[4]  = {0.f, 0.f, 0.f, 0.f};

    const size_t rowbase = ((size_t)b * S_) * D_ + h * DH_;

    for (int t0 = 0; t0 < S_; t0 += CH) {
        __syncthreads();
        for (int idx = tid; idx < CH * DH_; idx += 256) {
            int tt = idx >> 6, d = idx & 63;
            size_t g = rowbase + (size_t)(t0 + tt) * D_ + d;
            float qv = q[g], kv = k[g], vv = v[g];
            qv = qv > 0.f ? qv + 1.f : expf(qv);
            kv = kv > 0.f ? kv + 1.f : expf(kv);
            if (t0 + tt >= len) kv = 0.f;
            qs[tt][d] = qv; ks[tt][d] = kv; vs[tt][d] = vv;
        }
        __syncthreads();
#pragma unroll 4
        for (int tt = 0; tt < CH; tt++) {
            float4 k4 = *(const float4*)&ks[tt][d0];
            float4 q4 = *(const float4*)&qs[tt][d0];
            float ve = vs[tt][e];
            float np = 0.f, zp = 0.f;
            Sst[0] = fmaf(k4.x, ve, Sst[0]); cK[0] += k4.x;
            Sst[1] = fmaf(k4.y, ve, Sst[1]); cK[1] += k4.y;
            Sst[2] = fmaf(k4.z, ve, Sst[2]); cK[2] += k4.z;
            Sst[3] = fmaf(k4.w, ve, Sst[3]); cK[3] += k4.w;
            np = fmaf(q4.x, Sst[0], fmaf(q4.y, Sst[1], fmaf(q4.z, Sst[2], q4.w * Sst[3])));
            zp = fmaf(q4.x, cK[0],  fmaf(q4.y, cK[1],  fmaf(q4.z, cK[2],  q4.w * cK[3])));
#pragma unroll
            for (int o = 8; o > 0; o >>= 1) {
                np += __shfl_xor_sync(0xffffffffu, np, o);
                zp += __shfl_xor_sync(0xffffffffu, zp, o);
            }
            if (j == 0)
                out[rowbase + (size_t)(t0 + tt) * D_ + e] = np / (zp + EPS_);
        }
    }
}

// ---------------- residual + layernorm: out = LN(base + delta) * g + b ----------------
__global__ __launch_bounds__(128)
void ln_kernel(const float* __restrict__ base, const float* __restrict__ delta,
               const float* __restrict__ gam, const float* __restrict__ bet,
               float* __restrict__ out) {
    int row = blockIdx.x;
    int tid = threadIdx.x;           // 128 threads, one float4 each (D_=512)
    float4 x4 = ((const float4*)(base + (size_t)row * D_))[tid];
    if (delta != nullptr) {
        float4 d4 = ((const float4*)(delta + (size_t)row * D_))[tid];
        x4.x += d4.x; x4.y += d4.y; x4.z += d4.z; x4.w += d4.w;
    }
    float s  = x4.x + x4.y + x4.z + x4.w;
    float ss = x4.x * x4.x + x4.y * x4.y + x4.z * x4.z + x4.w * x4.w;
#pragma unroll
    for (int o = 16; o > 0; o >>= 1) {
        s  += __shfl_xor_sync(0xffffffffu, s, o);
        ss += __shfl_xor_sync(0xffffffffu, ss, o);
    }
    __shared__ float s1[4], s2[4];
    int wid = tid >> 5;
    if ((tid & 31) == 0) { s1[wid] = s; s2[wid] = ss; }
    __syncthreads();
    s  = s1[0] + s1[1] + s1[2] + s1[3];
    ss = s2[0] + s2[1] + s2[2] + s2[3];
    float mu  = s * (1.f / D_);
    float var = ss * (1.f / D_) - mu * mu;
    float rstd = rsqrtf(var + LN_EPS_);
    float4 g4 = ((const float4*)gam)[tid];
    float4 b4 = ((const float4*)bet)[tid];
    float4 o4;
    o4.x = (x4.x - mu) * rstd * g4.x + b4.x;
    o4.y = (x4.y - mu) * rstd * g4.y + b4.y;
    o4.z = (x4.z - mu) * rstd * g4.z + b4.z;
    o4.w = (x4.w - mu) * rstd * g4.w + b4.w;
    ((float4*)(out + (size_t)row * D_))[tid] = o4;
}

// ---------------- driver ----------------
extern "C" void kernel_launch(void* const* d_in, const int* in_sizes, int n_in,
                              void* d_out, int out_size) {
    const int*   x   = (const int*)  d_in[0];
    const float* emb = (const float*)d_in[1];
    const float* pe  = (const float*)d_in[2];
    const float* Wq  = (const float*)d_in[3];
    const float* bq  = (const float*)d_in[4];
    const float* Wk  = (const float*)d_in[5];
    const float* bk  = (const float*)d_in[6];
    const float* Wv  = (const float*)d_in[7];
    const float* bv  = (const float*)d_in[8];
    const float* Wo  = (const float*)d_in[9];
    const float* bo  = (const float*)d_in[10];
    const float* W1  = (const float*)d_in[11];
    const float* b1  = (const float*)d_in[12];
    const float* W2  = (const float*)d_in[13];
    const float* b2  = (const float*)d_in[14];
    const float* g1  = (const float*)d_in[15];
    const float* be1 = (const float*)d_in[16];
    const float* g2  = (const float*)d_in[17];
    const float* be2 = (const float*)d_in[18];
    const float* gf  = (const float*)d_in[19];
    const float* bf  = (const float*)d_in[20];
    float* out = (float*)d_out;

    float *p_h, *p_q, *p_k, *p_v, *p_attn, *p_tmp, *p_ffn;
    cudaGetSymbolAddress((void**)&p_h,    g_h);
    cudaGetSymbolAddress((void**)&p_q,    g_q);
    cudaGetSymbolAddress((void**)&p_k,    g_k);
    cudaGetSymbolAddress((void**)&p_v,    g_v);
    cudaGetSymbolAddress((void**)&p_attn, g_attn);
    cudaGetSymbolAddress((void**)&p_tmp,  g_tmp);
    cudaGetSymbolAddress((void**)&p_ffn,  g_ffn);

    lengths_kernel<<<B_, 256>>>(x);
    embed_kernel<<<BS_, 128>>>(x, emb, pe);

    dim3 gD(D_ / BN, BS_ / BM);   // (4, 64)  N=512
    dim3 gF(F_ / BN, BS_ / BM);   // (16, 64) N=2048

    for (int l = 0; l < NL_; l++) {
        const float* Wq_l = Wq + (size_t)l * D_ * D_;
        const float* Wk_l = Wk + (size_t)l * D_ * D_;
        const float* Wv_l = Wv + (size_t)l * D_ * D_;
        const float* Wo_l = Wo + (size_t)l * D_ * D_;
        const float* W1_l = W1 + (size_t)l * D_ * F_;
        const float* W2_l = W2 + (size_t)l * F_ * D_;
        const float* bq_l = bq + (size_t)l * D_;
        const float* bk_l = bk + (size_t)l * D_;
        const float* bv_l = bv + (size_t)l * D_;
        const float* bo_l = bo + (size_t)l * D_;
        const float* b1_l = b1 + (size_t)l * F_;
        const float* b2_l = b2 + (size_t)l * D_;

        sgemm_kernel<<<gD, 256>>>(p_h, Wq_l, bq_l, p_q, BS_, D_, D_, 0);
        sgemm_kernel<<<gD, 256>>>(p_h, Wk_l, bk_l, p_k, BS_, D_, D_, 0);
        sgemm_kernel<<<gD, 256>>>(p_h, Wv_l, bv_l, p_v, BS_, D_, D_, 0);

        attn_kernel<<<dim3(B_ * H_, 4), 256>>>(p_q, p_k, p_v, p_attn);

        sgemm_kernel<<<gD, 256>>>(p_attn, Wo_l, bo_l, p_tmp, BS_, D_, D_, 0);
        ln_kernel<<<BS_, 128>>>(p_h, p_tmp, g1 + (size_t)l * D_, be1 + (size_t)l * D_, p_h);

        sgemm_kernel<<<gF, 256>>>(p_h, W1_l, b1_l, p_ffn, BS_, F_, D_, 1);
        sgemm_kernel<<<gD, 256>>>(p_ffn, W2_l, b2_l, p_tmp, BS_, D_, F_, 0);
        ln_kernel<<<BS_, 128>>>(p_h, p_tmp, g2 + (size_t)l * D_, be2 + (size_t)l * D_, p_h);
    }

    ln_kernel<<<BS_, 128>>>(p_h, nullptr, gf, bf, out);
    (void)in_sizes; (void)n_in; (void)out_size;
}

// round 4
// speedup vs baseline: 1.8764x; 1.8764x over previous
#include <cuda_runtime.h>
#include <cuda_bf16.h>
#include <stdint.h>
#include <math.h>

#define B_  4
#define S_  2048
#define D_  512
#define H_  8
#define DH_ 64
#define F_  2048
#define NL_ 4
#define BS_ (B_*S_)          // 8192 rows
#define EPS_    1e-6f
#define LN_EPS_ 1e-5f

// ---------------- scratch (device globals; no allocation allowed) ----------------
__device__ float g_h   [BS_*D_];
__device__ float g_q   [BS_*D_];
__device__ float g_k   [BS_*D_];
__device__ float g_v   [BS_*D_];
__device__ float g_attn[BS_*D_];
__device__ float g_tmp [BS_*D_];
__device__ float g_ffn [BS_*F_];
__device__ int   g_len [B_];

// ---------------- lengths ----------------
__global__ void lengths_kernel(const int* __restrict__ x) {
    int b = blockIdx.x;
    int tid = threadIdx.x;
    __shared__ int sred[256];
    int cnt = 0;
    for (int s = tid; s < S_; s += 256) cnt += (x[b * S_ + s] != 0) ? 1 : 0;
    sred[tid] = cnt;
    __syncthreads();
    for (int o = 128; o > 0; o >>= 1) {
        if (tid < o) sred[tid] += sred[tid + o];
        __syncthreads();
    }
    if (tid == 0) g_len[b] = sred[0];
}

// ---------------- embedding + positional encoding ----------------
__global__ void embed_kernel(const int* __restrict__ x,
                             const float* __restrict__ emb,
                             const float* __restrict__ pe) {
    int row = blockIdx.x;
    int s = row % S_;
    int tok = x[row];
    const float4* e4 = (const float4*)(emb + (size_t)tok * D_);
    const float4* p4 = (const float4*)(pe + (size_t)s * D_);
    float4* h4 = (float4*)(g_h + (size_t)row * D_);
    int i = threadIdx.x;
    float4 a = e4[i], p = p4[i];
    h4[i] = make_float4(a.x + p.x, a.y + p.y, a.z + p.z, a.w + p.w);
}

// ---------------- tf32 tensor-core GEMM ----------------
// C[M,N] = A[M,K] @ B[K,N] + bias, optional relu
// 128x128 CTA tile, BK=16, double buffered, 8 warps (2x4), warp tile 64x32.
#define BM 128
#define BN 128
#define BKC 16
#define APAD 20    // As row stride (u32): (20*lr+lc)%32 distinct over lanes
#define BPAD 136   // Bs row stride (u32): (8*lc+lr)%32 distinct over lanes

__device__ __forceinline__ uint32_t f2tf(float f) {
    uint32_t u;
    asm("cvt.rna.tf32.f32 %0, %1;" : "=r"(u) : "f"(f));
    return u;
}

__device__ __forceinline__ void mma_tf32(float* c, const uint32_t* a, const uint32_t* b) {
    asm volatile(
        "mma.sync.aligned.m16n8k8.row.col.f32.tf32.tf32.f32 "
        "{%0,%1,%2,%3}, {%4,%5,%6,%7}, {%8,%9}, {%0,%1,%2,%3};"
        : "+f"(c[0]), "+f"(c[1]), "+f"(c[2]), "+f"(c[3])
        : "r"(a[0]), "r"(a[1]), "r"(a[2]), "r"(a[3]), "r"(b[0]), "r"(b[1]));
}

__global__ __launch_bounds__(256, 2)
void tgemm_kernel(const float* __restrict__ A, const float* __restrict__ Bm,
                  const float* __restrict__ bias, float* __restrict__ C,
                  int M, int N, int K, int relu) {
    __shared__ uint32_t As[2][BM][APAD];      // [row][k]
    __shared__ uint32_t Bs[2][BKC][BPAD];     // [k][n]

    const int tid = threadIdx.x;
    const int bx = blockIdx.x;   // N tile
    const int by = blockIdx.y;   // M tile
    const int w  = tid >> 5;
    const int lane = tid & 31;
    const int lr = lane >> 2;    // 0..7
    const int lc = lane & 3;     // 0..3
    const int wm = w >> 2;       // 0..1
    const int wn = w & 3;        // 0..3
    const int m0 = wm * 64;
    const int n0 = wn * 32;

    // loaders
    const int aRow = tid >> 2;          // 0..63  (+64 for i=1)
    const int aKq  = tid & 3;           // k-quad
    const int bK   = tid >> 5;          // 0..7   (+8 for i=1)
    const int bNq  = tid & 31;          // n-quad

    const float* Ag = A + ((size_t)(by * BM + aRow)) * K + aKq * 4;
    const float* Bg = Bm + (size_t)bK * N + bx * BN + bNq * 4;
    const size_t AgStep = (size_t)64 * K;
    const size_t BgStep = (size_t)8 * N;

    float acc[4][4][4];
#pragma unroll
    for (int i = 0; i < 4; i++)
#pragma unroll
        for (int j = 0; j < 4; j++)
#pragma unroll
            for (int r = 0; r < 4; r++) acc[i][j][r] = 0.f;

    float4 ra[2], rb[2];
    // prologue: chunk 0
    ra[0] = *(const float4*)(Ag);
    ra[1] = *(const float4*)(Ag + AgStep);
    rb[0] = *(const float4*)(Bg);
    rb[1] = *(const float4*)(Bg + BgStep);

#pragma unroll
    for (int i = 0; i < 2; i++) {
        float4 v = ra[i];
        uint4 p = make_uint4(f2tf(v.x), f2tf(v.y), f2tf(v.z), f2tf(v.w));
        *(uint4*)&As[0][aRow + 64 * i][aKq * 4] = p;
        float4 u = rb[i];
        uint4 q = make_uint4(f2tf(u.x), f2tf(u.y), f2tf(u.z), f2tf(u.w));
        *(uint4*)&Bs[0][bK + 8 * i][bNq * 4] = q;
    }
    __syncthreads();

    const int nChunks = K / BKC;
    int cur = 0;
    for (int c = 0; c < nChunks; c++) {
        if (c + 1 < nChunks) {
            const float* Ap = Ag + (size_t)(c + 1) * BKC;
            const float* Bp = Bg + (size_t)(c + 1) * BKC * N;
            ra[0] = *(const float4*)(Ap);
            ra[1] = *(const float4*)(Ap + AgStep);
            rb[0] = *(const float4*)(Bp);
            rb[1] = *(const float4*)(Bp + BgStep);
        }

#pragma unroll
        for (int ks = 0; ks < 2; ks++) {
            const int kb = ks * 8;
            uint32_t afr[4][4], bfr[4][2];
#pragma unroll
            for (int mt = 0; mt < 4; mt++) {
                int r = m0 + mt * 16 + lr;
                afr[mt][0] = As[cur][r][kb + lc];
                afr[mt][1] = As[cur][r + 8][kb + lc];
                afr[mt][2] = As[cur][r][kb + lc + 4];
                afr[mt][3] = As[cur][r + 8][kb + lc + 4];
            }
#pragma unroll
            for (int nt = 0; nt < 4; nt++) {
                int n = n0 + nt * 8 + lr;
                bfr[nt][0] = Bs[cur][kb + lc][n];
                bfr[nt][1] = Bs[cur][kb + lc + 4][n];
            }
#pragma unroll
            for (int mt = 0; mt < 4; mt++)
#pragma unroll
                for (int nt = 0; nt < 4; nt++)
                    mma_tf32(acc[mt][nt], afr[mt], bfr[nt]);
        }

        if (c + 1 < nChunks) {
            int nxt = cur ^ 1;
#pragma unroll
            for (int i = 0; i < 2; i++) {
                float4 v = ra[i];
                uint4 p = make_uint4(f2tf(v.x), f2tf(v.y), f2tf(v.z), f2tf(v.w));
                *(uint4*)&As[nxt][aRow + 64 * i][aKq * 4] = p;
                float4 u = rb[i];
                uint4 q = make_uint4(f2tf(u.x), f2tf(u.y), f2tf(u.z), f2tf(u.w));
                *(uint4*)&Bs[nxt][bK + 8 * i][bNq * 4] = q;
            }
            __syncthreads();
            cur = nxt;
        }
    }

    // epilogue: bias (+relu), write C
#pragma unroll
    for (int nt = 0; nt < 4; nt++) {
        int col = bx * BN + n0 + nt * 8 + 2 * lc;
        float bv0 = bias[col], bv1 = bias[col + 1];
#pragma unroll
        for (int mt = 0; mt < 4; mt++) {
            int row = by * BM + m0 + mt * 16 + lr;
            float o0 = acc[mt][nt][0] + bv0;
            float o1 = acc[mt][nt][1] + bv1;
            float o2 = acc[mt][nt][2] + bv0;
            float o3 = acc[mt][nt][3] + bv1;
            if (relu) {
                o0 = fmaxf(o0, 0.f); o1 = fmaxf(o1, 0.f);
                o2 = fmaxf(o2, 0.f); o3 = fmaxf(o3, 0.f);
            }
            *(float2*)(C + (size_t)row * N + col)       = make_float2(o0, o1);
            *(float2*)(C + (size_t)(row + 8) * N + col) = make_float2(o2, o3);
        }
    }
}

// ---------------- causal linear attention ----------------
#define CH 16
__global__ __launch_bounds__(256)
void attn_kernel(const float* __restrict__ q, const float* __restrict__ k,
                 const float* __restrict__ v, float* __restrict__ out) {
    int bh = blockIdx.x;
    int b = bh / H_, h = bh % H_;
    int tid = threadIdx.x;
    int e = blockIdx.y * 16 + (tid >> 4);
    int j = tid & 15;
    int d0 = j * 4;
    int len = g_len[b];

    __shared__ float qs[CH][DH_], ks[CH][DH_], vs[CH][DH_];

    float Sst[4] = {0.f, 0.f, 0.f, 0.f};
    float cK[4]  = {0.f, 0.f, 0.f, 0.f};

    const size_t rowbase = ((size_t)b * S_) * D_ + h * DH_;

    for (int t0 = 0; t0 < S_; t0 += CH) {
        __syncthreads();
        for (int idx = tid; idx < CH * DH_; idx += 256) {
            int tt = idx >> 6, d = idx & 63;
            size_t g = rowbase + (size_t)(t0 + tt) * D_ + d;
            float qv = q[g], kv = k[g], vv = v[g];
            qv = qv > 0.f ? qv + 1.f : expf(qv);
            kv = kv > 0.f ? kv + 1.f : expf(kv);
            if (t0 + tt >= len) kv = 0.f;
            qs[tt][d] = qv; ks[tt][d] = kv; vs[tt][d] = vv;
        }
        __syncthreads();
#pragma unroll 4
        for (int tt = 0; tt < CH; tt++) {
            float4 k4 = *(const float4*)&ks[tt][d0];
            float4 q4 = *(const float4*)&qs[tt][d0];
            float ve = vs[tt][e];
            float np, zp;
            Sst[0] = fmaf(k4.x, ve, Sst[0]); cK[0] += k4.x;
            Sst[1] = fmaf(k4.y, ve, Sst[1]); cK[1] += k4.y;
            Sst[2] = fmaf(k4.z, ve, Sst[2]); cK[2] += k4.z;
            Sst[3] = fmaf(k4.w, ve, Sst[3]); cK[3] += k4.w;
            np = fmaf(q4.x, Sst[0], fmaf(q4.y, Sst[1], fmaf(q4.z, Sst[2], q4.w * Sst[3])));
            zp = fmaf(q4.x, cK[0],  fmaf(q4.y, cK[1],  fmaf(q4.z, cK[2],  q4.w * cK[3])));
#pragma unroll
            for (int o = 8; o > 0; o >>= 1) {
                np += __shfl_xor_sync(0xffffffffu, np, o);
                zp += __shfl_xor_sync(0xffffffffu, zp, o);
            }
            if (j == 0)
                out[rowbase + (size_t)(t0 + tt) * D_ + e] = np / (zp + EPS_);
        }
    }
}

// ---------------- residual + layernorm ----------------
__global__ __launch_bounds__(128)
void ln_kernel(const float* __restrict__ base, const float* __restrict__ delta,
               const float* __restrict__ gam, const float* __restrict__ bet,
               float* __restrict__ out) {
    int row = blockIdx.x;
    int tid = threadIdx.x;
    float4 x4 = ((const float4*)(base + (size_t)row * D_))[tid];
    if (delta != nullptr) {
        float4 d4 = ((const float4*)(delta + (size_t)row * D_))[tid];
        x4.x += d4.x; x4.y += d4.y; x4.z += d4.z; x4.w += d4.w;
    }
    float s  = x4.x + x4.y + x4.z + x4.w;
    float ss = x4.x * x4.x + x4.y * x4.y + x4.z * x4.z + x4.w * x4.w;
#pragma unroll
    for (int o = 16; o > 0; o >>= 1) {
        s  += __shfl_xor_sync(0xffffffffu, s, o);
        ss += __shfl_xor_sync(0xffffffffu, ss, o);
    }
    __shared__ float s1[4], s2[4];
    int wid = tid >> 5;
    if ((tid & 31) == 0) { s1[wid] = s; s2[wid] = ss; }
    __syncthreads();
    s  = s1[0] + s1[1] + s1[2] + s1[3];
    ss = s2[0] + s2[1] + s2[2] + s2[3];
    float mu  = s * (1.f / D_);
    float var = ss * (1.f / D_) - mu * mu;
    float rstd = rsqrtf(var + LN_EPS_);
    float4 g4 = ((const float4*)gam)[tid];
    float4 b4 = ((const float4*)bet)[tid];
    float4 o4;
    o4.x = (x4.x - mu) * rstd * g4.x + b4.x;
    o4.y = (x4.y - mu) * rstd * g4.y + b4.y;
    o4.z = (x4.z - mu) * rstd * g4.z + b4.z;
    o4.w = (x4.w - mu) * rstd * g4.w + b4.w;
    ((float4*)(out + (size_t)row * D_))[tid] = o4;
}

// ---------------- driver ----------------
extern "C" void kernel_launch(void* const* d_in, const int* in_sizes, int n_in,
                              void* d_out, int out_size) {
    const int*   x   = (const int*)  d_in[0];
    const float* emb = (const float*)d_in[1];
    const float* pe  = (const float*)d_in[2];
    const float* Wq  = (const float*)d_in[3];
    const float* bq  = (const float*)d_in[4];
    const float* Wk  = (const float*)d_in[5];
    const float* bk  = (const float*)d_in[6];
    const float* Wv  = (const float*)d_in[7];
    const float* bv  = (const float*)d_in[8];
    const float* Wo  = (const float*)d_in[9];
    const float* bo  = (const float*)d_in[10];
    const float* W1  = (const float*)d_in[11];
    const float* b1  = (const float*)d_in[12];
    const float* W2  = (const float*)d_in[13];
    const float* b2  = (const float*)d_in[14];
    const float* g1  = (const float*)d_in[15];
    const float* be1 = (const float*)d_in[16];
    const float* g2  = (const float*)d_in[17];
    const float* be2 = (const float*)d_in[18];
    const float* gf  = (const float*)d_in[19];
    const float* bf  = (const float*)d_in[20];
    float* out = (float*)d_out;

    float *p_h, *p_q, *p_k, *p_v, *p_attn, *p_tmp, *p_ffn;
    cudaGetSymbolAddress((void**)&p_h,    g_h);
    cudaGetSymbolAddress((void**)&p_q,    g_q);
    cudaGetSymbolAddress((void**)&p_k,    g_k);
    cudaGetSymbolAddress((void**)&p_v,    g_v);
    cudaGetSymbolAddress((void**)&p_attn, g_attn);
    cudaGetSymbolAddress((void**)&p_tmp,  g_tmp);
    cudaGetSymbolAddress((void**)&p_ffn,  g_ffn);

    lengths_kernel<<<B_, 256>>>(x);
    embed_kernel<<<BS_, 128>>>(x, emb, pe);

    dim3 gD(D_ / BN, BS_ / BM);   // (4, 64)
    dim3 gF(F_ / BN, BS_ / BM);   // (16, 64)

    for (int l = 0; l < NL_; l++) {
        const float* Wq_l = Wq + (size_t)l * D_ * D_;
        const float* Wk_l = Wk + (size_t)l * D_ * D_;
        const float* Wv_l = Wv + (size_t)l * D_ * D_;
        const float* Wo_l = Wo + (size_t)l * D_ * D_;
        const float* W1_l = W1 + (size_t)l * D_ * F_;
        const float* W2_l = W2 + (size_t)l * F_ * D_;
        const float* bq_l = bq + (size_t)l * D_;
        const float* bk_l = bk + (size_t)l * D_;
        const float* bv_l = bv + (size_t)l * D_;
        const float* bo_l = bo + (size_t)l * D_;
        const float* b1_l = b1 + (size_t)l * F_;
        const float* b2_l = b2 + (size_t)l * D_;

        tgemm_kernel<<<gD, 256>>>(p_h, Wq_l, bq_l, p_q, BS_, D_, D_, 0);
        tgemm_kernel<<<gD, 256>>>(p_h, Wk_l, bk_l, p_k, BS_, D_, D_, 0);
        tgemm_kernel<<<gD, 256>>>(p_h, Wv_l, bv_l, p_v, BS_, D_, D_, 0);

        attn_kernel<<<dim3(B_ * H_, 4), 256>>>(p_q, p_k, p_v, p_attn);

        tgemm_kernel<<<gD, 256>>>(p_attn, Wo_l, bo_l, p_tmp, BS_, D_, D_, 0);
        ln_kernel<<<BS_, 128>>>(p_h, p_tmp, g1 + (size_t)l * D_, be1 + (size_t)l * D_, p_h);

        tgemm_kernel<<<gF, 256>>>(p_h, W1_l, b1_l, p_ffn, BS_, F_, D_, 1);
        tgemm_kernel<<<gD, 256>>>(p_ffn, W2_l, b2_l, p_tmp, BS_, D_, F_, 0);
        ln_kernel<<<BS_, 128>>>(p_h, p_tmp, g2 + (size_t)l * D_, be2 + (size_t)l * D_, p_h);
    }

    ln_kernel<<<BS_, 128>>>(p_h, nullptr, gf, bf, out);
    (void)in_sizes; (void)n_in; (void)out_size;
}

// round 5
// speedup vs baseline: 3.3227x; 1.7708x over previous
#include <cuda_runtime.h>
#include <cuda_bf16.h>
#include <stdint.h>
#include <math.h>

#define B_  4
#define S_  2048
#define D_  512
#define H_  8
#define DH_ 64
#define F_  2048
#define NL_ 4
#define BS_ (B_*S_)          // 8192 rows
#define EPS_    1e-6f
#define LN_EPS_ 1e-5f

#define CT  64               // attention chunk length
#define NC  (S_/CT)          // 32 chunks
#define BH  (B_*H_)          // 32 batch-heads

// ---------------- scratch (device globals; no allocation allowed) ----------------
__device__ float g_h   [BS_*D_];
__device__ float g_q   [BS_*D_];
__device__ float g_k   [BS_*D_];
__device__ float g_v   [BS_*D_];
__device__ float g_attn[BS_*D_];
__device__ float g_tmp [BS_*D_];
__device__ float g_ffn [BS_*F_];
__device__ float g_G   [(size_t)BH*NC*DH_*DH_];   // per-chunk K^T V
__device__ float g_Sp  [(size_t)BH*NC*DH_*DH_];   // exclusive prefix of G
__device__ float g_ck  [BH*NC*DH_];               // per-chunk colsum K
__device__ float g_ckp [BH*NC*DH_];               // exclusive prefix
__device__ int   g_len [B_];

// ---------------- lengths ----------------
__global__ void lengths_kernel(const int* __restrict__ x) {
    int b = blockIdx.x;
    int tid = threadIdx.x;
    __shared__ int sred[256];
    int cnt = 0;
    for (int s = tid; s < S_; s += 256) cnt += (x[b * S_ + s] != 0) ? 1 : 0;
    sred[tid] = cnt;
    __syncthreads();
    for (int o = 128; o > 0; o >>= 1) {
        if (tid < o) sred[tid] += sred[tid + o];
        __syncthreads();
    }
    if (tid == 0) g_len[b] = sred[0];
}

// ---------------- embedding + positional encoding ----------------
__global__ void embed_kernel(const int* __restrict__ x,
                             const float* __restrict__ emb,
                             const float* __restrict__ pe) {
    int row = blockIdx.x;
    int s = row % S_;
    int tok = x[row];
    const float4* e4 = (const float4*)(emb + (size_t)tok * D_);
    const float4* p4 = (const float4*)(pe + (size_t)s * D_);
    float4* h4 = (float4*)(g_h + (size_t)row * D_);
    int i = threadIdx.x;
    float4 a = e4[i], p = p4[i];
    h4[i] = make_float4(a.x + p.x, a.y + p.y, a.z + p.z, a.w + p.w);
}

// ---------------- tf32 tensor-core GEMM ----------------
#define BM 128
#define BN 128
#define BKC 16
#define APAD 20
#define BPAD 136

__device__ __forceinline__ uint32_t f2tf(float f) {
    uint32_t u;
    asm("cvt.rna.tf32.f32 %0, %1;" : "=r"(u) : "f"(f));
    return u;
}

__device__ __forceinline__ void mma_tf32(float* c, const uint32_t* a, const uint32_t* b) {
    asm volatile(
        "mma.sync.aligned.m16n8k8.row.col.f32.tf32.tf32.f32 "
        "{%0,%1,%2,%3}, {%4,%5,%6,%7}, {%8,%9}, {%0,%1,%2,%3};"
        : "+f"(c[0]), "+f"(c[1]), "+f"(c[2]), "+f"(c[3])
        : "r"(a[0]), "r"(a[1]), "r"(a[2]), "r"(a[3]), "r"(b[0]), "r"(b[1]));
}

__global__ __launch_bounds__(256, 2)
void tgemm_kernel(const float* __restrict__ A, const float* __restrict__ Bm,
                  const float* __restrict__ bias, float* __restrict__ C,
                  int M, int N, int K, int relu) {
    __shared__ uint32_t As[2][BM][APAD];
    __shared__ uint32_t Bs[2][BKC][BPAD];

    const int tid = threadIdx.x;
    const int bx = blockIdx.x;
    const int by = blockIdx.y;
    const int w  = tid >> 5;
    const int lane = tid & 31;
    const int lr = lane >> 2;
    const int lc = lane & 3;
    const int wm = w >> 2;
    const int wn = w & 3;
    const int m0 = wm * 64;
    const int n0 = wn * 32;

    const int aRow = tid >> 2;
    const int aKq  = tid & 3;
    const int bK   = tid >> 5;
    const int bNq  = tid & 31;

    const float* Ag = A + ((size_t)(by * BM + aRow)) * K + aKq * 4;
    const float* Bg = Bm + (size_t)bK * N + bx * BN + bNq * 4;
    const size_t AgStep = (size_t)64 * K;
    const size_t BgStep = (size_t)8 * N;

    float acc[4][4][4];
#pragma unroll
    for (int i = 0; i < 4; i++)
#pragma unroll
        for (int j = 0; j < 4; j++)
#pragma unroll
            for (int r = 0; r < 4; r++) acc[i][j][r] = 0.f;

    float4 ra[2], rb[2];
    ra[0] = *(const float4*)(Ag);
    ra[1] = *(const float4*)(Ag + AgStep);
    rb[0] = *(const float4*)(Bg);
    rb[1] = *(const float4*)(Bg + BgStep);

#pragma unroll
    for (int i = 0; i < 2; i++) {
        float4 v = ra[i];
        uint4 p = make_uint4(f2tf(v.x), f2tf(v.y), f2tf(v.z), f2tf(v.w));
        *(uint4*)&As[0][aRow + 64 * i][aKq * 4] = p;
        float4 u = rb[i];
        uint4 q = make_uint4(f2tf(u.x), f2tf(u.y), f2tf(u.z), f2tf(u.w));
        *(uint4*)&Bs[0][bK + 8 * i][bNq * 4] = q;
    }
    __syncthreads();

    const int nChunks = K / BKC;
    int cur = 0;
    for (int c = 0; c < nChunks; c++) {
        if (c + 1 < nChunks) {
            const float* Ap = Ag + (size_t)(c + 1) * BKC;
            const float* Bp = Bg + (size_t)(c + 1) * BKC * N;
            ra[0] = *(const float4*)(Ap);
            ra[1] = *(const float4*)(Ap + AgStep);
            rb[0] = *(const float4*)(Bp);
            rb[1] = *(const float4*)(Bp + BgStep);
        }

#pragma unroll
        for (int ks = 0; ks < 2; ks++) {
            const int kb = ks * 8;
            uint32_t afr[4][4], bfr[4][2];
#pragma unroll
            for (int mt = 0; mt < 4; mt++) {
                int r = m0 + mt * 16 + lr;
                afr[mt][0] = As[cur][r][kb + lc];
                afr[mt][1] = As[cur][r + 8][kb + lc];
                afr[mt][2] = As[cur][r][kb + lc + 4];
                afr[mt][3] = As[cur][r + 8][kb + lc + 4];
            }
#pragma unroll
            for (int nt = 0; nt < 4; nt++) {
                int n = n0 + nt * 8 + lr;
                bfr[nt][0] = Bs[cur][kb + lc][n];
                bfr[nt][1] = Bs[cur][kb + lc + 4][n];
            }
#pragma unroll
            for (int mt = 0; mt < 4; mt++)
#pragma unroll
                for (int nt = 0; nt < 4; nt++)
                    mma_tf32(acc[mt][nt], afr[mt], bfr[nt]);
        }

        if (c + 1 < nChunks) {
            int nxt = cur ^ 1;
#pragma unroll
            for (int i = 0; i < 2; i++) {
                float4 v = ra[i];
                uint4 p = make_uint4(f2tf(v.x), f2tf(v.y), f2tf(v.z), f2tf(v.w));
                *(uint4*)&As[nxt][aRow + 64 * i][aKq * 4] = p;
                float4 u = rb[i];
                uint4 q = make_uint4(f2tf(u.x), f2tf(u.y), f2tf(u.z), f2tf(u.w));
                *(uint4*)&Bs[nxt][bK + 8 * i][bNq * 4] = q;
            }
            __syncthreads();
            cur = nxt;
        }
    }

#pragma unroll
    for (int nt = 0; nt < 4; nt++) {
        int col = bx * BN + n0 + nt * 8 + 2 * lc;
        float bv0 = bias[col], bv1 = bias[col + 1];
#pragma unroll
        for (int mt = 0; mt < 4; mt++) {
            int row = by * BM + m0 + mt * 16 + lr;
            float o0 = acc[mt][nt][0] + bv0;
            float o1 = acc[mt][nt][1] + bv1;
            float o2 = acc[mt][nt][2] + bv0;
            float o3 = acc[mt][nt][3] + bv1;
            if (relu) {
                o0 = fmaxf(o0, 0.f); o1 = fmaxf(o1, 0.f);
                o2 = fmaxf(o2, 0.f); o3 = fmaxf(o3, 0.f);
            }
            *(float2*)(C + (size_t)row * N + col)       = make_float2(o0, o1);
            *(float2*)(C + (size_t)(row + 8) * N + col) = make_float2(o2, o3);
        }
    }
}

// ================= chunked causal linear attention =================
__device__ __forceinline__ float phi_f(float x) {
    return x > 0.f ? x + 1.f : expf(x);
}

// Pass 1: per (bh, chunk): G = K^T V (64x64), cumK = colsum(K). phi+mask applied to K.
__global__ __launch_bounds__(256)
void attn_kv_kernel(const float* __restrict__ k, const float* __restrict__ v) {
    int blk = blockIdx.x;
    int bh = blk / NC, c = blk % NC;
    int b = bh / H_, h = bh % H_;
    int len = g_len[b];
    int tid = threadIdx.x;

    __shared__ float Ks[CT][DH_];
    __shared__ float Vs[CT][DH_];

    size_t base = ((size_t)b * S_ + (size_t)c * CT) * D_ + h * DH_;

#pragma unroll
    for (int it = 0; it < 4; it++) {
        int idx = tid + it * 256;            // 0..1023 float4s
        int t = idx >> 4, d4 = (idx & 15) * 4;
        float4 kv = *(const float4*)(k + base + (size_t)t * D_ + d4);
        float4 vv = *(const float4*)(v + base + (size_t)t * D_ + d4);
        float m = ((c * CT + t) < len) ? 1.f : 0.f;
        kv.x = phi_f(kv.x) * m; kv.y = phi_f(kv.y) * m;
        kv.z = phi_f(kv.z) * m; kv.w = phi_f(kv.w) * m;
        *(float4*)&Ks[t][d4] = kv;
        *(float4*)&Vs[t][d4] = vv;
    }
    __syncthreads();

    int d0 = (tid & 15) * 4;
    int e0 = (tid >> 4) * 4;
    float acc[4][4];
#pragma unroll
    for (int i = 0; i < 4; i++)
#pragma unroll
        for (int j = 0; j < 4; j++) acc[i][j] = 0.f;

    for (int t = 0; t < CT; t++) {
        float4 kd = *(const float4*)&Ks[t][d0];
        float4 ve = *(const float4*)&Vs[t][e0];
        float kdx[4] = {kd.x, kd.y, kd.z, kd.w};
        float vex[4] = {ve.x, ve.y, ve.z, ve.w};
#pragma unroll
        for (int i = 0; i < 4; i++)
#pragma unroll
            for (int j = 0; j < 4; j++)
                acc[i][j] = fmaf(kdx[i], vex[j], acc[i][j]);
    }

    float* Gout = g_G + ((size_t)bh * NC + c) * (DH_ * DH_);
#pragma unroll
    for (int i = 0; i < 4; i++) {
        *(float4*)&Gout[(size_t)(d0 + i) * DH_ + e0] =
            make_float4(acc[i][0], acc[i][1], acc[i][2], acc[i][3]);
    }

    // cumK
    if (tid < DH_) {
        float s = 0.f;
        for (int t = 0; t < CT; t++) s += Ks[t][tid];
        g_ck[((size_t)bh * NC + c) * DH_ + tid] = s;
    }
}

// Pass 2: exclusive prefix over chunks. grid (BH, 16), 256 threads.
__global__ __launch_bounds__(256)
void attn_prefix_kernel() {
    int bh = blockIdx.x;
    int e = blockIdx.y * 256 + threadIdx.x;    // 0..4095
    const float* G = g_G + (size_t)bh * NC * (DH_ * DH_);
    float* Sp = g_Sp + (size_t)bh * NC * (DH_ * DH_);
    float run = 0.f;
    for (int c = 0; c < NC; c++) {
        Sp[(size_t)c * (DH_ * DH_) + e] = run;
        run += G[(size_t)c * (DH_ * DH_) + e];
    }
    if (blockIdx.y == 0 && threadIdx.x < DH_) {
        int d = threadIdx.x;
        float r2 = 0.f;
        for (int c = 0; c < NC; c++) {
            g_ckp[((size_t)bh * NC + c) * DH_ + d] = r2;
            r2 += g_ck[((size_t)bh * NC + c) * DH_ + d];
        }
    }
}

// Pass 3: per (bh, chunk): A = phiQ phiK^T masked; out = (A V + phiQ Sprev) / z.
#define SMP 68   // padded row stride (floats), multiple of 4 for float4 alignment
__global__ __launch_bounds__(256)
void attn_out_kernel(const float* __restrict__ q, const float* __restrict__ k,
                     const float* __restrict__ v, float* __restrict__ out) {
    extern __shared__ float sm[];
    float* Qs  = sm;                       // [64][SMP]
    float* Xs  = sm + 64 * SMP;            // [64][SMP]
    float* As  = sm + 2 * 64 * SMP;        // [64][SMP]
    float* zs  = sm + 3 * 64 * SMP;        // [64]
    float* ckp = zs + 64;                  // [64]

    int blk = blockIdx.x;
    int bh = blk / NC, c = blk % NC;
    int b = bh / H_, h = bh % H_;
    int len = g_len[b];
    int tid = threadIdx.x;

    size_t base = ((size_t)b * S_ + (size_t)c * CT) * D_ + h * DH_;

    if (tid < DH_) ckp[tid] = g_ckp[((size_t)bh * NC + c) * DH_ + tid];

    // load Q (phi) and K (phi+mask)
#pragma unroll
    for (int it = 0; it < 4; it++) {
        int idx = tid + it * 256;
        int t = idx >> 4, d4 = (idx & 15) * 4;
        float4 qv = *(const float4*)(q + base + (size_t)t * D_ + d4);
        float4 kv = *(const float4*)(k + base + (size_t)t * D_ + d4);
        qv.x = phi_f(qv.x); qv.y = phi_f(qv.y);
        qv.z = phi_f(qv.z); qv.w = phi_f(qv.w);
        float m = ((c * CT + t) < len) ? 1.f : 0.f;
        kv.x = phi_f(kv.x) * m; kv.y = phi_f(kv.y) * m;
        kv.z = phi_f(kv.z) * m; kv.w = phi_f(kv.w) * m;
        *(float4*)&Qs[t * SMP + d4] = qv;
        *(float4*)&Xs[t * SMP + d4] = kv;
    }
    __syncthreads();

    // A[i][j] = Qs[i]·Xs[j], causal mask j<=i
    {
        int i0 = (tid >> 4) * 4;
        int j0 = (tid & 15) * 4;
        float acc[4][4];
#pragma unroll
        for (int i = 0; i < 4; i++)
#pragma unroll
            for (int j = 0; j < 4; j++) acc[i][j] = 0.f;

        for (int d = 0; d < DH_; d += 4) {
            float4 qa[4], kb[4];
#pragma unroll
            for (int i = 0; i < 4; i++) qa[i] = *(const float4*)&Qs[(i0 + i) * SMP + d];
#pragma unroll
            for (int j = 0; j < 4; j++) kb[j] = *(const float4*)&Xs[(j0 + j) * SMP + d];
#pragma unroll
            for (int i = 0; i < 4; i++)
#pragma unroll
                for (int j = 0; j < 4; j++)
                    acc[i][j] += qa[i].x * kb[j].x + qa[i].y * kb[j].y
                               + qa[i].z * kb[j].z + qa[i].w * kb[j].w;
        }
#pragma unroll
        for (int i = 0; i < 4; i++) {
            float4 row;
            row.x = (j0 + 0 <= i0 + i) ? acc[i][0] : 0.f;
            row.y = (j0 + 1 <= i0 + i) ? acc[i][1] : 0.f;
            row.z = (j0 + 2 <= i0 + i) ? acc[i][2] : 0.f;
            row.w = (j0 + 3 <= i0 + i) ? acc[i][3] : 0.f;
            *(float4*)&As[(i0 + i) * SMP + j0] = row;
        }
    }
    __syncthreads();

    // z[i] = rowsum(A[i]) + Qs[i]·ckp ; also load V into Xs
    if (tid < CT) {
        int i = tid;
        float z = 0.f;
        for (int j = 0; j < CT; j++) z += As[i * SMP + j];
        for (int d = 0; d < DH_; d++) z += Qs[i * SMP + d] * ckp[d];
        zs[i] = z;
    }
#pragma unroll
    for (int it = 0; it < 4; it++) {
        int idx = tid + it * 256;
        int t = idx >> 4, d4 = (idx & 15) * 4;
        float4 vv = *(const float4*)(v + base + (size_t)t * D_ + d4);
        *(float4*)&Xs[t * SMP + d4] = vv;
    }
    __syncthreads();

    // num = A V  (then += phiQ Sprev)
    int i0 = (tid >> 4) * 4;
    int e0 = (tid & 15) * 4;
    float acc2[4][4];
#pragma unroll
    for (int i = 0; i < 4; i++)
#pragma unroll
        for (int j = 0; j < 4; j++) acc2[i][j] = 0.f;

    for (int j = 0; j < CT; j++) {
        float a0 = As[(i0 + 0) * SMP + j];
        float a1 = As[(i0 + 1) * SMP + j];
        float a2 = As[(i0 + 2) * SMP + j];
        float a3 = As[(i0 + 3) * SMP + j];
        float4 vj = *(const float4*)&Xs[j * SMP + e0];
        acc2[0][0] = fmaf(a0, vj.x, acc2[0][0]); acc2[0][1] = fmaf(a0, vj.y, acc2[0][1]);
        acc2[0][2] = fmaf(a0, vj.z, acc2[0][2]); acc2[0][3] = fmaf(a0, vj.w, acc2[0][3]);
        acc2[1][0] = fmaf(a1, vj.x, acc2[1][0]); acc2[1][1] = fmaf(a1, vj.y, acc2[1][1]);
        acc2[1][2] = fmaf(a1, vj.z, acc2[1][2]); acc2[1][3] = fmaf(a1, vj.w, acc2[1][3]);
        acc2[2][0] = fmaf(a2, vj.x, acc2[2][0]); acc2[2][1] = fmaf(a2, vj.y, acc2[2][1]);
        acc2[2][2] = fmaf(a2, vj.z, acc2[2][2]); acc2[2][3] = fmaf(a2, vj.w, acc2[2][3]);
        acc2[3][0] = fmaf(a3, vj.x, acc2[3][0]); acc2[3][1] = fmaf(a3, vj.y, acc2[3][1]);
        acc2[3][2] = fmaf(a3, vj.z, acc2[3][2]); acc2[3][3] = fmaf(a3, vj.w, acc2[3][3]);
    }
    __syncthreads();

    // load Sprev into As
    {
        const float* Sp = g_Sp + ((size_t)bh * NC + c) * (DH_ * DH_);
#pragma unroll
        for (int it = 0; it < 4; it++) {
            int idx = tid + it * 256;
            int d = idx >> 4, e4 = (idx & 15) * 4;
            float4 sv = *(const float4*)(Sp + (size_t)d * DH_ + e4);
            *(float4*)&As[d * SMP + e4] = sv;
        }
    }
    __syncthreads();

    // num += phiQ · Sprev
    for (int d = 0; d < DH_; d++) {
        float q0 = Qs[(i0 + 0) * SMP + d];
        float q1 = Qs[(i0 + 1) * SMP + d];
        float q2 = Qs[(i0 + 2) * SMP + d];
        float q3 = Qs[(i0 + 3) * SMP + d];
        float4 sd = *(const float4*)&As[d * SMP + e0];
        acc2[0][0] = fmaf(q0, sd.x, acc2[0][0]); acc2[0][1] = fmaf(q0, sd.y, acc2[0][1]);
        acc2[0][2] = fmaf(q0, sd.z, acc2[0][2]); acc2[0][3] = fmaf(q0, sd.w, acc2[0][3]);
        acc2[1][0] = fmaf(q1, sd.x, acc2[1][0]); acc2[1][1] = fmaf(q1, sd.y, acc2[1][1]);
        acc2[1][2] = fmaf(q1, sd.z, acc2[1][2]); acc2[1][3] = fmaf(q1, sd.w, acc2[1][3]);
        acc2[2][0] = fmaf(q2, sd.x, acc2[2][0]); acc2[2][1] = fmaf(q2, sd.y, acc2[2][1]);
        acc2[2][2] = fmaf(q2, sd.z, acc2[2][2]); acc2[2][3] = fmaf(q2, sd.w, acc2[2][3]);
        acc2[3][0] = fmaf(q3, sd.x, acc2[3][0]); acc2[3][1] = fmaf(q3, sd.y, acc2[3][1]);
        acc2[3][2] = fmaf(q3, sd.z, acc2[3][2]); acc2[3][3] = fmaf(q3, sd.w, acc2[3][3]);
    }

#pragma unroll
    for (int i = 0; i < 4; i++) {
        float inv = 1.f / (zs[i0 + i] + EPS_);
        float4 o;
        o.x = acc2[i][0] * inv; o.y = acc2[i][1] * inv;
        o.z = acc2[i][2] * inv; o.w = acc2[i][3] * inv;
        *(float4*)(out + base + (size_t)(i0 + i) * D_ + e0) = o;
    }
}
#define SM3_BYTES ((3*64*SMP + 128) * 4)

// ---------------- residual + layernorm ----------------
__global__ __launch_bounds__(128)
void ln_kernel(const float* __restrict__ base, const float* __restrict__ delta,
               const float* __restrict__ gam, const float* __restrict__ bet,
               float* __restrict__ out) {
    int row = blockIdx.x;
    int tid = threadIdx.x;
    float4 x4 = ((const float4*)(base + (size_t)row * D_))[tid];
    if (delta != nullptr) {
        float4 d4 = ((const float4*)(delta + (size_t)row * D_))[tid];
        x4.x += d4.x; x4.y += d4.y; x4.z += d4.z; x4.w += d4.w;
    }
    float s  = x4.x + x4.y + x4.z + x4.w;
    float ss = x4.x * x4.x + x4.y * x4.y + x4.z * x4.z + x4.w * x4.w;
#pragma unroll
    for (int o = 16; o > 0; o >>= 1) {
        s  += __shfl_xor_sync(0xffffffffu, s, o);
        ss += __shfl_xor_sync(0xffffffffu, ss, o);
    }
    __shared__ float s1[4], s2[4];
    int wid = tid >> 5;
    if ((tid & 31) == 0) { s1[wid] = s; s2[wid] = ss; }
    __syncthreads();
    s  = s1[0] + s1[1] + s1[2] + s1[3];
    ss = s2[0] + s2[1] + s2[2] + s2[3];
    float mu  = s * (1.f / D_);
    float var = ss * (1.f / D_) - mu * mu;
    float rstd = rsqrtf(var + LN_EPS_);
    float4 g4 = ((const float4*)gam)[tid];
    float4 b4 = ((const float4*)bet)[tid];
    float4 o4;
    o4.x = (x4.x - mu) * rstd * g4.x + b4.x;
    o4.y = (x4.y - mu) * rstd * g4.y + b4.y;
    o4.z = (x4.z - mu) * rstd * g4.z + b4.z;
    o4.w = (x4.w - mu) * rstd * g4.w + b4.w;
    ((float4*)(out + (size_t)row * D_))[tid] = o4;
}

// ---------------- driver ----------------
extern "C" void kernel_launch(void* const* d_in, const int* in_sizes, int n_in,
                              void* d_out, int out_size) {
    const int*   x   = (const int*)  d_in[0];
    const float* emb = (const float*)d_in[1];
    const float* pe  = (const float*)d_in[2];
    const float* Wq  = (const float*)d_in[3];
    const float* bq  = (const float*)d_in[4];
    const float* Wk  = (const float*)d_in[5];
    const float* bk  = (const float*)d_in[6];
    const float* Wv  = (const float*)d_in[7];
    const float* bv  = (const float*)d_in[8];
    const float* Wo  = (const float*)d_in[9];
    const float* bo  = (const float*)d_in[10];
    const float* W1  = (const float*)d_in[11];
    const float* b1  = (const float*)d_in[12];
    const float* W2  = (const float*)d_in[13];
    const float* b2  = (const float*)d_in[14];
    const float* g1  = (const float*)d_in[15];
    const float* be1 = (const float*)d_in[16];
    const float* g2  = (const float*)d_in[17];
    const float* be2 = (const float*)d_in[18];
    const float* gf  = (const float*)d_in[19];
    const float* bf  = (const float*)d_in[20];
    float* out = (float*)d_out;

    float *p_h, *p_q, *p_k, *p_v, *p_attn, *p_tmp, *p_ffn;
    cudaGetSymbolAddress((void**)&p_h,    g_h);
    cudaGetSymbolAddress((void**)&p_q,    g_q);
    cudaGetSymbolAddress((void**)&p_k,    g_k);
    cudaGetSymbolAddress((void**)&p_v,    g_v);
    cudaGetSymbolAddress((void**)&p_attn, g_attn);
    cudaGetSymbolAddress((void**)&p_tmp,  g_tmp);
    cudaGetSymbolAddress((void**)&p_ffn,  g_ffn);

    cudaFuncSetAttribute(attn_out_kernel,
                         cudaFuncAttributeMaxDynamicSharedMemorySize, SM3_BYTES);

    lengths_kernel<<<B_, 256>>>(x);
    embed_kernel<<<BS_, 128>>>(x, emb, pe);

    dim3 gD(D_ / BN, BS_ / BM);   // (4, 64)
    dim3 gF(F_ / BN, BS_ / BM);   // (16, 64)

    for (int l = 0; l < NL_; l++) {
        const float* Wq_l = Wq + (size_t)l * D_ * D_;
        const float* Wk_l = Wk + (size_t)l * D_ * D_;
        const float* Wv_l = Wv + (size_t)l * D_ * D_;
        const float* Wo_l = Wo + (size_t)l * D_ * D_;
        const float* W1_l = W1 + (size_t)l * D_ * F_;
        const float* W2_l = W2 + (size_t)l * F_ * D_;
        const float* bq_l = bq + (size_t)l * D_;
        const float* bk_l = bk + (size_t)l * D_;
        const float* bv_l = bv + (size_t)l * D_;
        const float* bo_l = bo + (size_t)l * D_;
        const float* b1_l = b1 + (size_t)l * F_;
        const float* b2_l = b2 + (size_t)l * D_;

        tgemm_kernel<<<gD, 256>>>(p_h, Wq_l, bq_l, p_q, BS_, D_, D_, 0);
        tgemm_kernel<<<gD, 256>>>(p_h, Wk_l, bk_l, p_k, BS_, D_, D_, 0);
        tgemm_kernel<<<gD, 256>>>(p_h, Wv_l, bv_l, p_v, BS_, D_, D_, 0);

        attn_kv_kernel<<<BH * NC, 256>>>(p_k, p_v);
        attn_prefix_kernel<<<dim3(BH, 16), 256>>>();
        attn_out_kernel<<<BH * NC, 256, SM3_BYTES>>>(p_q, p_k, p_v, p_attn);

        tgemm_kernel<<<gD, 256>>>(p_attn, Wo_l, bo_l, p_tmp, BS_, D_, D_, 0);
        ln_kernel<<<BS_, 128>>>(p_h, p_tmp, g1 + (size_t)l * D_, be1 + (size_t)l * D_, p_h);

        tgemm_kernel<<<gF, 256>>>(p_h, W1_l, b1_l, p_ffn, BS_, F_, D_, 1);
        tgemm_kernel<<<gD, 256>>>(p_ffn, W2_l, b2_l, p_tmp, BS_, D_, F_, 0);
        ln_kernel<<<BS_, 128>>>(p_h, p_tmp, g2 + (size_t)l * D_, be2 + (size_t)l * D_, p_h);
    }

    ln_kernel<<<BS_, 128>>>(p_h, nullptr, gf, bf, out);
    (void)in_sizes; (void)n_in; (void)out_size;
}

// round 8
// speedup vs baseline: 3.6791x; 1.1073x over previous
#include <cuda_runtime.h>
#include <cuda_bf16.h>
#include <stdint.h>
#include <math.h>

#define B_  4
#define S_  2048
#define D_  512
#define H_  8
#define DH_ 64
#define F_  2048
#define NL_ 4
#define BS_ (B_*S_)          // 8192 rows
#define EPS_    1e-6f
#define LN_EPS_ 1e-5f

#define CT  64               // attention chunk length
#define NC  (S_/CT)          // 32 chunks
#define BH  (B_*H_)          // 32 batch-heads

#define LW_ ((size_t)4*D_*D_ + 2*(size_t)D_*F_)   // weight elems per layer

// ---------------- scratch (device globals; no allocation allowed) ----------------
__device__ float g_h   [BS_*D_];
__device__ float g_hr  [BS_*D_];     // tf32-rounded copy of h
__device__ float g_q   [BS_*D_];
__device__ float g_k   [BS_*D_];
__device__ float g_v   [BS_*D_];
__device__ float g_attn[BS_*D_];
__device__ float g_tmp [BS_*D_];
__device__ float g_ffn [BS_*F_];
__device__ float g_wr  [NL_*LW_];    // tf32-rounded weights (original [K][N] layout)
__device__ float g_G   [(size_t)BH*NC*DH_*DH_];
__device__ float g_Sp  [(size_t)BH*NC*DH_*DH_];
__device__ float g_ck  [BH*NC*DH_];
__device__ float g_ckp [BH*NC*DH_];
__device__ int   g_len [B_];

__device__ __forceinline__ uint32_t f2tf(float f) {
    uint32_t u;
    asm("cvt.rna.tf32.f32 %0, %1;" : "=r"(u) : "f"(f));
    return u;
}
__device__ __forceinline__ float rtf(float f) { return __uint_as_float(f2tf(f)); }

__device__ __forceinline__ uint32_t smem_u32(const void* p) {
    uint32_t a;
    asm("{ .reg .u64 t; cvta.to.shared.u64 t, %1; cvt.u32.u64 %0, t; }" : "=r"(a) : "l"(p));
    return a;
}
__device__ __forceinline__ void cp16(uint32_t dst, const void* src) {
    asm volatile("cp.async.cg.shared.global [%0], [%1], 16;" :: "r"(dst), "l"(src));
}

// ---------------- lengths ----------------
__global__ void lengths_kernel(const int* __restrict__ x) {
    int b = blockIdx.x;
    int tid = threadIdx.x;
    __shared__ int sred[256];
    int cnt = 0;
    for (int s = tid; s < S_; s += 256) cnt += (x[b * S_ + s] != 0) ? 1 : 0;
    sred[tid] = cnt;
    __syncthreads();
    for (int o = 128; o > 0; o >>= 1) {
        if (tid < o) sred[tid] += sred[tid + o];
        __syncthreads();
    }
    if (tid == 0) g_len[b] = sred[0];
}

// ---------------- embedding + positional encoding (writes h and rounded h) ----------------
__global__ void embed_kernel(const int* __restrict__ x,
                             const float* __restrict__ emb,
                             const float* __restrict__ pe) {
    int row = blockIdx.x;
    int s = row % S_;
    int tok = x[row];
    const float4* e4 = (const float4*)(emb + (size_t)tok * D_);
    const float4* p4 = (const float4*)(pe + (size_t)s * D_);
    int i = threadIdx.x;
    float4 a = e4[i], p = p4[i];
    float4 o = make_float4(a.x + p.x, a.y + p.y, a.z + p.z, a.w + p.w);
    ((float4*)(g_h + (size_t)row * D_))[i] = o;
    ((float4*)(g_hr + (size_t)row * D_))[i] =
        make_float4(rtf(o.x), rtf(o.y), rtf(o.z), rtf(o.w));
}

// ---------------- round fp32 -> tf32-in-fp32 ----------------
__global__ void round_kernel(const float* __restrict__ src, float* __restrict__ dst, int n4) {
    int i = blockIdx.x * blockDim.x + threadIdx.x;
    if (i < n4) {
        float4 v = ((const float4*)src)[i];
        ((float4*)dst)[i] = make_float4(rtf(v.x), rtf(v.y), rtf(v.z), rtf(v.w));
    }
}

// ---------------- tf32 tensor-core GEMM, 3-stage cp.async ----------------
// Inputs MUST be pre-rounded to tf32. C = A[M,K] @ B[K,N] + bias; flags: 1=relu, 2=round output.
#define BKG 32
#define ASTR 36     // A smem row stride (floats): banks (4*lr+lc) conflict-free
#define BSTR 136    // B smem row stride (floats): banks (8*lc+lr) conflict-free
#define STG_A (128*ASTR)            // floats
#define STG_B (BKG*BSTR)
#define STG_FL (STG_A + STG_B)      // 8960 floats = 35840 B
#define GSM_BYTES (3 * STG_FL * 4)  // 107520

__device__ __forceinline__ void mma_tf32(float* c, const uint32_t* a, const uint32_t* b) {
    asm volatile(
        "mma.sync.aligned.m16n8k8.row.col.f32.tf32.tf32.f32 "
        "{%0,%1,%2,%3}, {%4,%5,%6,%7}, {%8,%9}, {%0,%1,%2,%3};"
        : "+f"(c[0]), "+f"(c[1]), "+f"(c[2]), "+f"(c[3])
        : "r"(a[0]), "r"(a[1]), "r"(a[2]), "r"(a[3]), "r"(b[0]), "r"(b[1]));
}

__global__ __launch_bounds__(256, 2)
void tgemm_kernel(const float* __restrict__ A, const float* __restrict__ Bm,
                  const float* __restrict__ bias, float* __restrict__ C,
                  int M, int N, int K, int flags) {
    extern __shared__ float smf[];
    const int tid = threadIdx.x;
    const int bx = blockIdx.x, by = blockIdx.y;
    const int lane = tid & 31;
    const int w = tid >> 5;
    const int lr = lane >> 2, lc = lane & 3;
    const int m0 = (w >> 2) * 64;
    const int n0 = (w & 3) * 32;

    // loader indices (4 chunks A + 4 chunks B per thread per stage)
    const int am = tid >> 3;           // +32*i  -> rows 0..127
    const int akq = tid & 7;           // 16B chunk in k
    const int bk = tid >> 5;           // +8*i   -> rows 0..31
    const int bnq = tid & 31;          // 16B chunk in n

    const float* Ag = A + (size_t)(by * 128 + am) * K + akq * 4;
    const float* Bg = Bm + (size_t)bk * N + bx * 128 + bnq * 4;

    const int T = K >> 5;
    uint32_t sb = smem_u32(smf);

    // stage loader
    auto load_stage = [&](int s, int t) {
        uint32_t abase = sb + (uint32_t)(s * STG_FL) * 4;
        uint32_t bbase = abase + (uint32_t)STG_A * 4;
        const float* ap = Ag + (size_t)t * BKG;
        const float* bp = Bg + (size_t)t * BKG * N;
#pragma unroll
        for (int i = 0; i < 4; i++) {
            cp16(abase + (uint32_t)((am + 32 * i) * ASTR + akq * 4) * 4,
                 ap + (size_t)(32 * i) * K);
            cp16(bbase + (uint32_t)((bk + 8 * i) * BSTR + bnq * 4) * 4,
                 bp + (size_t)(8 * i) * N);
        }
    };

    float acc[4][4][4];
#pragma unroll
    for (int i = 0; i < 4; i++)
#pragma unroll
        for (int j = 0; j < 4; j++)
#pragma unroll
            for (int r = 0; r < 4; r++) acc[i][j][r] = 0.f;

    load_stage(0, 0);
    asm volatile("cp.async.commit_group;" ::: "memory");
    if (T > 1) load_stage(1, 1);
    asm volatile("cp.async.commit_group;" ::: "memory");

    for (int t = 0; t < T; t++) {
        asm volatile("cp.async.wait_group 1;" ::: "memory");
        __syncthreads();
        if (t + 2 < T) load_stage((t + 2) % 3, t + 2);
        asm volatile("cp.async.commit_group;" ::: "memory");

        const float* As = smf + (t % 3) * STG_FL;
        const float* Bs = As + STG_A;
#pragma unroll
        for (int ks = 0; ks < 4; ks++) {
            const int kb = ks * 8;
            uint32_t afr[4][4], bfr[4][2];
#pragma unroll
            for (int mt = 0; mt < 4; mt++) {
                int r = m0 + mt * 16 + lr;
                afr[mt][0] = __float_as_uint(As[r * ASTR + kb + lc]);
                afr[mt][1] = __float_as_uint(As[(r + 8) * ASTR + kb + lc]);
                afr[mt][2] = __float_as_uint(As[r * ASTR + kb + lc + 4]);
                afr[mt][3] = __float_as_uint(As[(r + 8) * ASTR + kb + lc + 4]);
            }
#pragma unroll
            for (int nt = 0; nt < 4; nt++) {
                int n = n0 + nt * 8 + lr;
                bfr[nt][0] = __float_as_uint(Bs[(kb + lc) * BSTR + n]);
                bfr[nt][1] = __float_as_uint(Bs[(kb + lc + 4) * BSTR + n]);
            }
#pragma unroll
            for (int mt = 0; mt < 4; mt++)
#pragma unroll
                for (int nt = 0; nt < 4; nt++)
                    mma_tf32(acc[mt][nt], afr[mt], bfr[nt]);
        }
        __syncthreads();
    }

    const int relu = flags & 1, rnd = flags & 2;
#pragma unroll
    for (int nt = 0; nt < 4; nt++) {
        int col = bx * 128 + n0 + nt * 8 + 2 * lc;
        float bv0 = __ldg(&bias[col]), bv1 = __ldg(&bias[col + 1]);
#pragma unroll
        for (int mt = 0; mt < 4; mt++) {
            int row = by * 128 + m0 + mt * 16 + lr;
            float o0 = acc[mt][nt][0] + bv0;
            float o1 = acc[mt][nt][1] + bv1;
            float o2 = acc[mt][nt][2] + bv0;
            float o3 = acc[mt][nt][3] + bv1;
            if (relu) {
                o0 = fmaxf(o0, 0.f); o1 = fmaxf(o1, 0.f);
                o2 = fmaxf(o2, 0.f); o3 = fmaxf(o3, 0.f);
            }
            if (rnd) { o0 = rtf(o0); o1 = rtf(o1); o2 = rtf(o2); o3 = rtf(o3); }
            *(float2*)(C + (size_t)row * N + col)       = make_float2(o0, o1);
            *(float2*)(C + (size_t)(row + 8) * N + col) = make_float2(o2, o3);
        }
    }
}

// ================= chunked causal linear attention =================
__device__ __forceinline__ float phi_f(float x) {
    return x > 0.f ? x + 1.f : expf(x);
}

__global__ __launch_bounds__(256)
void attn_kv_kernel(const float* __restrict__ k, const float* __restrict__ v) {
    int blk = blockIdx.x;
    int bh = blk / NC, c = blk % NC;
    int b = bh / H_, h = bh % H_;
    int len = g_len[b];
    int tid = threadIdx.x;

    __shared__ float Ks[CT][DH_];
    __shared__ float Vs[CT][DH_];

    size_t base = ((size_t)b * S_ + (size_t)c * CT) * D_ + h * DH_;

#pragma unroll
    for (int it = 0; it < 4; it++) {
        int idx = tid + it * 256;
        int t = idx >> 4, d4 = (idx & 15) * 4;
        float4 kv = *(const float4*)(k + base + (size_t)t * D_ + d4);
        float4 vv = *(const float4*)(v + base + (size_t)t * D_ + d4);
        float m = ((c * CT + t) < len) ? 1.f : 0.f;
        kv.x = phi_f(kv.x) * m; kv.y = phi_f(kv.y) * m;
        kv.z = phi_f(kv.z) * m; kv.w = phi_f(kv.w) * m;
        *(float4*)&Ks[t][d4] = kv;
        *(float4*)&Vs[t][d4] = vv;
    }
    __syncthreads();

    int d0 = (tid & 15) * 4;
    int e0 = (tid >> 4) * 4;
    float acc[4][4];
#pragma unroll
    for (int i = 0; i < 4; i++)
#pragma unroll
        for (int j = 0; j < 4; j++) acc[i][j] = 0.f;

    for (int t = 0; t < CT; t++) {
        float4 kd = *(const float4*)&Ks[t][d0];
        float4 ve = *(const float4*)&Vs[t][e0];
        float kdx[4] = {kd.x, kd.y, kd.z, kd.w};
        float vex[4] = {ve.x, ve.y, ve.z, ve.w};
#pragma unroll
        for (int i = 0; i < 4; i++)
#pragma unroll
            for (int j = 0; j < 4; j++)
                acc[i][j] = fmaf(kdx[i], vex[j], acc[i][j]);
    }

    float* Gout = g_G + ((size_t)bh * NC + c) * (DH_ * DH_);
#pragma unroll
    for (int i = 0; i < 4; i++) {
        *(float4*)&Gout[(size_t)(d0 + i) * DH_ + e0] =
            make_float4(acc[i][0], acc[i][1], acc[i][2], acc[i][3]);
    }

    if (tid < DH_) {
        float s = 0.f;
        for (int t = 0; t < CT; t++) s += Ks[t][tid];
        g_ck[((size_t)bh * NC + c) * DH_ + tid] = s;
    }
}

__global__ __launch_bounds__(256)
void attn_prefix_kernel() {
    int bh = blockIdx.x;
    int e = blockIdx.y * 256 + threadIdx.x;
    const float* G = g_G + (size_t)bh * NC * (DH_ * DH_);
    float* Sp = g_Sp + (size_t)bh * NC * (DH_ * DH_);
    float run = 0.f;
    for (int c = 0; c < NC; c++) {
        Sp[(size_t)c * (DH_ * DH_) + e] = run;
        run += G[(size_t)c * (DH_ * DH_) + e];
    }
    if (blockIdx.y == 0 && threadIdx.x < DH_) {
        int d = threadIdx.x;
        float r2 = 0.f;
        for (int c = 0; c < NC; c++) {
            g_ckp[((size_t)bh * NC + c) * DH_ + d] = r2;
            r2 += g_ck[((size_t)bh * NC + c) * DH_ + d];
        }
    }
}

#define SMP 68
__global__ __launch_bounds__(256)
void attn_out_kernel(const float* __restrict__ q, const float* __restrict__ k,
                     const float* __restrict__ v, float* __restrict__ out) {
    extern __shared__ float sm[];
    float* Qs  = sm;
    float* Xs  = sm + 64 * SMP;
    float* As  = sm + 2 * 64 * SMP;
    float* zs  = sm + 3 * 64 * SMP;
    float* ckp = zs + 64;

    int blk = blockIdx.x;
    int bh = blk / NC, c = blk % NC;
    int b = bh / H_, h = bh % H_;
    int len = g_len[b];
    int tid = threadIdx.x;

    size_t base = ((size_t)b * S_ + (size_t)c * CT) * D_ + h * DH_;

    if (tid < DH_) ckp[tid] = g_ckp[((size_t)bh * NC + c) * DH_ + tid];

#pragma unroll
    for (int it = 0; it < 4; it++) {
        int idx = tid + it * 256;
        int t = idx >> 4, d4 = (idx & 15) * 4;
        float4 qv = *(const float4*)(q + base + (size_t)t * D_ + d4);
        float4 kv = *(const float4*)(k + base + (size_t)t * D_ + d4);
        qv.x = phi_f(qv.x); qv.y = phi_f(qv.y);
        qv.z = phi_f(qv.z); qv.w = phi_f(qv.w);
        float m = ((c * CT + t) < len) ? 1.f : 0.f;
        kv.x = phi_f(kv.x) * m; kv.y = phi_f(kv.y) * m;
        kv.z = phi_f(kv.z) * m; kv.w = phi_f(kv.w) * m;
        *(float4*)&Qs[t * SMP + d4] = qv;
        *(float4*)&Xs[t * SMP + d4] = kv;
    }
    __syncthreads();

    {
        int i0 = (tid >> 4) * 4;
        int j0 = (tid & 15) * 4;
        float acc[4][4];
#pragma unroll
        for (int i = 0; i < 4; i++)
#pragma unroll
            for (int j = 0; j < 4; j++) acc[i][j] = 0.f;

        for (int d = 0; d < DH_; d += 4) {
            float4 qa[4], kb[4];
#pragma unroll
            for (int i = 0; i < 4; i++) qa[i] = *(const float4*)&Qs[(i0 + i) * SMP + d];
#pragma unroll
            for (int j = 0; j < 4; j++) kb[j] = *(const float4*)&Xs[(j0 + j) * SMP + d];
#pragma unroll
            for (int i = 0; i < 4; i++)
#pragma unroll
                for (int j = 0; j < 4; j++)
                    acc[i][j] += qa[i].x * kb[j].x + qa[i].y * kb[j].y
                               + qa[i].z * kb[j].z + qa[i].w * kb[j].w;
        }
#pragma unroll
        for (int i = 0; i < 4; i++) {
            float4 row;
            row.x = (j0 + 0 <= i0 + i) ? acc[i][0] : 0.f;
            row.y = (j0 + 1 <= i0 + i) ? acc[i][1] : 0.f;
            row.z = (j0 + 2 <= i0 + i) ? acc[i][2] : 0.f;
            row.w = (j0 + 3 <= i0 + i) ? acc[i][3] : 0.f;
            *(float4*)&As[(i0 + i) * SMP + j0] = row;
        }
    }
    __syncthreads();

    if (tid < CT) {
        int i = tid;
        float z = 0.f;
        for (int j = 0; j < CT; j++) z += As[i * SMP + j];
        for (int d = 0; d < DH_; d++) z += Qs[i * SMP + d] * ckp[d];
        zs[i] = z;
    }
#pragma unroll
    for (int it = 0; it < 4; it++) {
        int idx = tid + it * 256;
        int t = idx >> 4, d4 = (idx & 15) * 4;
        float4 vv = *(const float4*)(v + base + (size_t)t * D_ + d4);
        *(float4*)&Xs[t * SMP + d4] = vv;
    }
    __syncthreads();

    int i0 = (tid >> 4) * 4;
    int e0 = (tid & 15) * 4;
    float acc2[4][4];
#pragma unroll
    for (int i = 0; i < 4; i++)
#pragma unroll
        for (int j = 0; j < 4; j++) acc2[i][j] = 0.f;

    for (int j = 0; j < CT; j++) {
        float a0 = As[(i0 + 0) * SMP + j];
        float a1 = As[(i0 + 1) * SMP + j];
        float a2 = As[(i0 + 2) * SMP + j];
        float a3 = As[(i0 + 3) * SMP + j];
        float4 vj = *(const float4*)&Xs[j * SMP + e0];
        acc2[0][0] = fmaf(a0, vj.x, acc2[0][0]); acc2[0][1] = fmaf(a0, vj.y, acc2[0][1]);
        acc2[0][2] = fmaf(a0, vj.z, acc2[0][2]); acc2[0][3] = fmaf(a0, vj.w, acc2[0][3]);
        acc2[1][0] = fmaf(a1, vj.x, acc2[1][0]); acc2[1][1] = fmaf(a1, vj.y, acc2[1][1]);
        acc2[1][2] = fmaf(a1, vj.z, acc2[1][2]); acc2[1][3] = fmaf(a1, vj.w, acc2[1][3]);
        acc2[2][0] = fmaf(a2, vj.x, acc2[2][0]); acc2[2][1] = fmaf(a2, vj.y, acc2[2][1]);
        acc2[2][2] = fmaf(a2, vj.z, acc2[2][2]); acc2[2][3] = fmaf(a2, vj.w, acc2[2][3]);
        acc2[3][0] = fmaf(a3, vj.x, acc2[3][0]); acc2[3][1] = fmaf(a3, vj.y, acc2[3][1]);
        acc2[3][2] = fmaf(a3, vj.z, acc2[3][2]); acc2[3][3] = fmaf(a3, vj.w, acc2[3][3]);
    }
    __syncthreads();

    {
        const float* Sp = g_Sp + ((size_t)bh * NC + c) * (DH_ * DH_);
#pragma unroll
        for (int it = 0; it < 4; it++) {
            int idx = tid + it * 256;
            int d = idx >> 4, e4 = (idx & 15) * 4;
            float4 sv = *(const float4*)(Sp + (size_t)d * DH_ + e4);
            *(float4*)&As[d * SMP + e4] = sv;
        }
    }
    __syncthreads();

    for (int d = 0; d < DH_; d++) {
        float q0 = Qs[(i0 + 0) * SMP + d];
        float q1 = Qs[(i0 + 1) * SMP + d];
        float q2 = Qs[(i0 + 2) * SMP + d];
        float q3 = Qs[(i0 + 3) * SMP + d];
        float4 sd = *(const float4*)&As[d * SMP + e0];
        acc2[0][0] = fmaf(q0, sd.x, acc2[0][0]); acc2[0][1] = fmaf(q0, sd.y, acc2[0][1]);
        acc2[0][2] = fmaf(q0, sd.z, acc2[0][2]); acc2[0][3] = fmaf(q0, sd.w, acc2[0][3]);
        acc2[1][0] = fmaf(q1, sd.x, acc2[1][0]); acc2[1][1] = fmaf(q1, sd.y, acc2[1][1]);
        acc2[1][2] = fmaf(q1, sd.z, acc2[1][2]); acc2[1][3] = fmaf(q1, sd.w, acc2[1][3]);
        acc2[2][0] = fmaf(q2, sd.x, acc2[2][0]); acc2[2][1] = fmaf(q2, sd.y, acc2[2][1]);
        acc2[2][2] = fmaf(q2, sd.z, acc2[2][2]); acc2[2][3] = fmaf(q2, sd.w, acc2[2][3]);
        acc2[3][0] = fmaf(q3, sd.x, acc2[3][0]); acc2[3][1] = fmaf(q3, sd.y, acc2[3][1]);
        acc2[3][2] = fmaf(q3, sd.z, acc2[3][2]); acc2[3][3] = fmaf(q3, sd.w, acc2[3][3]);
    }

#pragma unroll
    for (int i = 0; i < 4; i++) {
        float inv = 1.f / (zs[i0 + i] + EPS_);
        float4 o;
        o.x = rtf(acc2[i][0] * inv); o.y = rtf(acc2[i][1] * inv);
        o.z = rtf(acc2[i][2] * inv); o.w = rtf(acc2[i][3] * inv);
        *(float4*)(out + base + (size_t)(i0 + i) * D_ + e0) = o;
    }
}
#define SM3_BYTES ((3*64*SMP + 128) * 4)

// ---------------- residual + layernorm (writes exact + optional rounded) ----------------
__global__ __launch_bounds__(128)
void ln_kernel(const float* __restrict__ base, const float* __restrict__ delta,
               const float* __restrict__ gam, const float* __restrict__ bet,
               float* __restrict__ out, float* __restrict__ out_r) {
    int row = blockIdx.x;
    int tid = threadIdx.x;
    float4 x4 = ((const float4*)(base + (size_t)row * D_))[tid];
    if (delta != nullptr) {
        float4 d4 = ((const float4*)(delta + (size_t)row * D_))[tid];
        x4.x += d4.x; x4.y += d4.y; x4.z += d4.z; x4.w += d4.w;
    }
    float s  = x4.x + x4.y + x4.z + x4.w;
    float ss = x4.x * x4.x + x4.y * x4.y + x4.z * x4.z + x4.w * x4.w;
#pragma unroll
    for (int o = 16; o > 0; o >>= 1) {
        s  += __shfl_xor_sync(0xffffffffu, s, o);
        ss += __shfl_xor_sync(0xffffffffu, ss, o);
    }
    __shared__ float s1[4], s2[4];
    int wid = tid >> 5;
    if ((tid & 31) == 0) { s1[wid] = s; s2[wid] = ss; }
    __syncthreads();
    s  = s1[0] + s1[1] + s1[2] + s1[3];
    ss = s2[0] + s2[1] + s2[2] + s2[3];
    float mu  = s * (1.f / D_);
    float var = ss * (1.f / D_) - mu * mu;
    float rstd = rsqrtf(var + LN_EPS_);
    float4 g4 = ((const float4*)gam)[tid];
    float4 b4 = ((const float4*)bet)[tid];
    float4 o4;
    o4.x = (x4.x - mu) * rstd * g4.x + b4.x;
    o4.y = (x4.y - mu) * rstd * g4.y + b4.y;
    o4.z = (x4.z - mu) * rstd * g4.z + b4.z;
    o4.w = (x4.w - mu) * rstd * g4.w + b4.w;
    ((float4*)(out + (size_t)row * D_))[tid] = o4;
    if (out_r != nullptr)
        ((float4*)(out_r + (size_t)row * D_))[tid] =
            make_float4(rtf(o4.x), rtf(o4.y), rtf(o4.z), rtf(o4.w));
}

// ---------------- driver ----------------
extern "C" void kernel_launch(void* const* d_in, const int* in_sizes, int n_in,
                              void* d_out, int out_size) {
    const int*   x   = (const int*)  d_in[0];
    const float* emb = (const float*)d_in[1];
    const float* pe  = (const float*)d_in[2];
    const float* Wq  = (const float*)d_in[3];
    const float* bq  = (const float*)d_in[4];
    const float* Wk  = (const float*)d_in[5];
    const float* bk  = (const float*)d_in[6];
    const float* Wv  = (const float*)d_in[7];
    const float* bv  = (const float*)d_in[8];
    const float* Wo  = (const float*)d_in[9];
    const float* bo  = (const float*)d_in[10];
    const float* W1  = (const float*)d_in[11];
    const float* b1  = (const float*)d_in[12];
    const float* W2  = (const float*)d_in[13];
    const float* b2  = (const float*)d_in[14];
    const float* g1  = (const float*)d_in[15];
    const float* be1 = (const float*)d_in[16];
    const float* g2  = (const float*)d_in[17];
    const float* be2 = (const float*)d_in[18];
    const float* gf  = (const float*)d_in[19];
    const float* bf  = (const float*)d_in[20];
    float* out = (float*)d_out;

    float *p_h, *p_hr, *p_q, *p_k, *p_v, *p_attn, *p_tmp, *p_ffn, *p_wr;
    cudaGetSymbolAddress((void**)&p_h,    g_h);
    cudaGetSymbolAddress((void**)&p_hr,   g_hr);
    cudaGetSymbolAddress((void**)&p_q,    g_q);
    cudaGetSymbolAddress((void**)&p_k,    g_k);
    cudaGetSymbolAddress((void**)&p_v,    g_v);
    cudaGetSymbolAddress((void**)&p_attn, g_attn);
    cudaGetSymbolAddress((void**)&p_tmp,  g_tmp);
    cudaGetSymbolAddress((void**)&p_ffn,  g_ffn);
    cudaGetSymbolAddress((void**)&p_wr,   g_wr);

    cudaFuncSetAttribute(attn_out_kernel,
                         cudaFuncAttributeMaxDynamicSharedMemorySize, SM3_BYTES);
    cudaFuncSetAttribute(tgemm_kernel,
                         cudaFuncAttributeMaxDynamicSharedMemorySize, GSM_BYTES);

    lengths_kernel<<<B_, 256>>>(x);
    embed_kernel<<<BS_, 128>>>(x, emb, pe);

    // round all weights to tf32 once (into g_wr, original [K][N] layouts)
    {
        const int TPB = 256;
        int nDD = (D_ * D_) / 4, nDF = (D_ * F_) / 4;
        for (int l = 0; l < NL_; l++) {
            size_t base = (size_t)l * LW_;
            round_kernel<<<(nDD + TPB - 1) / TPB, TPB>>>(Wq + (size_t)l*D_*D_, p_wr + base,               nDD);
            round_kernel<<<(nDD + TPB - 1) / TPB, TPB>>>(Wk + (size_t)l*D_*D_, p_wr + base + 1u*D_*D_,    nDD);
            round_kernel<<<(nDD + TPB - 1) / TPB, TPB>>>(Wv + (size_t)l*D_*D_, p_wr + base + 2u*D_*D_,    nDD);
            round_kernel<<<(nDD + TPB - 1) / TPB, TPB>>>(Wo + (size_t)l*D_*D_, p_wr + base + 3u*D_*D_,    nDD);
            round_kernel<<<(nDF + TPB - 1) / TPB, TPB>>>(W1 + (size_t)l*D_*F_, p_wr + base + 4u*D_*D_,    nDF);
            round_kernel<<<(nDF + TPB - 1) / TPB, TPB>>>(W2 + (size_t)l*F_*D_, p_wr + base + 4u*D_*D_ + (size_t)D_*F_, nDF);
        }
    }

    dim3 gD(D_ / 128, BS_ / 128);   // (4, 64)
    dim3 gF(F_ / 128, BS_ / 128);   // (16, 64)

    for (int l = 0; l < NL_; l++) {
        size_t base = (size_t)l * LW_;
        const float *wq = p_wr + base;
        const float *wk = wq + (size_t)D_*D_;
        const float *wv = wq + 2u*(size_t)D_*D_;
        const float *wo = wq + 3u*(size_t)D_*D_;
        const float *w1 = wq + 4u*(size_t)D_*D_;
        const float *w2 = w1 + (size_t)D_*F_;
        const float* bq_l = bq + (size_t)l * D_;
        const float* bk_l = bk + (size_t)l * D_;
        const float* bv_l = bv + (size_t)l * D_;
        const float* bo_l = bo + (size_t)l * D_;
        const float* b1_l = b1 + (size_t)l * F_;
        const float* b2_l = b2 + (size_t)l * D_;

        tgemm_kernel<<<gD, 256, GSM_BYTES>>>(p_hr, wq, bq_l, p_q, BS_, D_, D_, 0);
        tgemm_kernel<<<gD, 256, GSM_BYTES>>>(p_hr, wk, bk_l, p_k, BS_, D_, D_, 0);
        tgemm_kernel<<<gD, 256, GSM_BYTES>>>(p_hr, wv, bv_l, p_v, BS_, D_, D_, 0);

        attn_kv_kernel<<<BH * NC, 256>>>(p_k, p_v);
        attn_prefix_kernel<<<dim3(BH, 16), 256>>>();
        attn_out_kernel<<<BH * NC, 256, SM3_BYTES>>>(p_q, p_k, p_v, p_attn);

        tgemm_kernel<<<gD, 256, GSM_BYTES>>>(p_attn, wo, bo_l, p_tmp, BS_, D_, D_, 0);
        ln_kernel<<<BS_, 128>>>(p_h, p_tmp, g1 + (size_t)l * D_, be1 + (size_t)l * D_, p_h, p_hr);

        tgemm_kernel<<<gF, 256, GSM_BYTES>>>(p_hr, w1, b1_l, p_ffn, BS_, F_, D_, 1 | 2);
        tgemm_kernel<<<gD, 256, GSM_BYTES>>>(p_ffn, w2, b2_l, p_tmp, BS_, D_, F_, 0);
        ln_kernel<<<BS_, 128>>>(p_h, p_tmp, g2 + (size_t)l * D_, be2 + (size_t)l * D_, p_h, p_hr);
    }

    ln_kernel<<<BS_, 128>>>(p_h, nullptr, gf, bf, out, nullptr);
    (void)in_sizes; (void)n_in; (void)out_size;
}

// round 9
// speedup vs baseline: 3.7997x; 1.0328x over previous
#include <cuda_runtime.h>
#include <cuda_bf16.h>
#include <stdint.h>
#include <math.h>

#define B_  4
#define S_  2048
#define D_  512
#define H_  8
#define DH_ 64
#define F_  2048
#define NL_ 4
#define BS_ (B_*S_)          // 8192 rows
#define EPS_    1e-6f
#define LN_EPS_ 1e-5f

#define CT  64               // attention chunk length
#define NC  (S_/CT)          // 32 chunks
#define BH  (B_*H_)          // 32 batch-heads
#define QS_ 1536             // packed qkv row stride

// packed per-layer layout: [Wqkv 512x1536][Wo 512x512][W1 512x2048][W2 2048x512][bqkv 1536]
#define R_QKV  (D_*3*D_)                 // 786432
#define R_WO   (D_*D_)                   // 262144
#define R_W1   (D_*F_)                   // 1048576
#define R_W2   (F_*D_)                   // 1048576
#define LW_    ((size_t)R_QKV + R_WO + R_W1 + R_W2)   // 3145728
#define LWP_   (LW_ + QS_)               // + packed qkv bias

// ---------------- scratch (device globals; no allocation allowed) ----------------
__device__ float g_h   [BS_*D_];
__device__ float g_hr  [BS_*D_];     // tf32-rounded copy of h
__device__ float g_qkv [(size_t)BS_*QS_];
__device__ float g_attn[BS_*D_];
__device__ float g_tmp [BS_*D_];
__device__ float g_ffn [BS_*F_];
__device__ float g_wr  [NL_*LWP_];   // packed tf32-rounded weights + qkv bias
__device__ float g_G   [(size_t)BH*NC*DH_*DH_];
__device__ float g_Sp  [(size_t)BH*NC*DH_*DH_];
__device__ float g_ck  [BH*NC*DH_];
__device__ float g_ckp [BH*NC*DH_];
__device__ int   g_len [B_];

__device__ __forceinline__ uint32_t f2tf(float f) {
    uint32_t u;
    asm("cvt.rna.tf32.f32 %0, %1;" : "=r"(u) : "f"(f));
    return u;
}
__device__ __forceinline__ float rtf(float f) { return __uint_as_float(f2tf(f)); }

__device__ __forceinline__ uint32_t smem_u32(const void* p) {
    uint32_t a;
    asm("{ .reg .u64 t; cvta.to.shared.u64 t, %1; cvt.u32.u64 %0, t; }" : "=r"(a) : "l"(p));
    return a;
}
__device__ __forceinline__ void cp16(uint32_t dst, const void* src) {
    asm volatile("cp.async.cg.shared.global [%0], [%1], 16;" :: "r"(dst), "l"(src));
}

// ---------------- lengths ----------------
__global__ void lengths_kernel(const int* __restrict__ x) {
    int b = blockIdx.x;
    int tid = threadIdx.x;
    __shared__ int sred[256];
    int cnt = 0;
    for (int s = tid; s < S_; s += 256) cnt += (x[b * S_ + s] != 0) ? 1 : 0;
    sred[tid] = cnt;
    __syncthreads();
    for (int o = 128; o > 0; o >>= 1) {
        if (tid < o) sred[tid] += sred[tid + o];
        __syncthreads();
    }
    if (tid == 0) g_len[b] = sred[0];
}

// ---------------- embedding + positional encoding (writes h and rounded h) ----------------
__global__ void embed_kernel(const int* __restrict__ x,
                             const float* __restrict__ emb,
                             const float* __restrict__ pe) {
    int row = blockIdx.x;
    int s = row % S_;
    int tok = x[row];
    const float4* e4 = (const float4*)(emb + (size_t)tok * D_);
    const float4* p4 = (const float4*)(pe + (size_t)s * D_);
    int i = threadIdx.x;
    float4 a = e4[i], p = p4[i];
    float4 o = make_float4(a.x + p.x, a.y + p.y, a.z + p.z, a.w + p.w);
    ((float4*)(g_h + (size_t)row * D_))[i] = o;
    ((float4*)(g_hr + (size_t)row * D_))[i] =
        make_float4(rtf(o.x), rtf(o.y), rtf(o.z), rtf(o.w));
}

// ---------------- pack: round + lay out all weights (one launch) ----------------
__global__ void pack_kernel(const float* __restrict__ Wq, const float* __restrict__ Wk,
                            const float* __restrict__ Wv, const float* __restrict__ Wo,
                            const float* __restrict__ W1, const float* __restrict__ W2,
                            const float* __restrict__ bq, const float* __restrict__ bk,
                            const float* __restrict__ bv) {
    const size_t total4 = (size_t)NL_ * LWP_ / 4;
    for (size_t i4 = (size_t)blockIdx.x * blockDim.x + threadIdx.x; i4 < total4;
         i4 += (size_t)gridDim.x * blockDim.x) {
        size_t e = i4 * 4;
        int l = (int)(e / LWP_);
        size_t r = e % LWP_;
        const float* src;
        int is_bias = 0;
        if (r < R_QKV) {
            int k = (int)(r / QS_), n = (int)(r % QS_);
            const float* W = (n < D_) ? Wq : (n < 2 * D_) ? Wk : Wv;
            int nn = (n < D_) ? n : (n < 2 * D_) ? n - D_ : n - 2 * D_;
            src = W + (size_t)l * D_ * D_ + (size_t)k * D_ + nn;
        } else if (r < (size_t)R_QKV + R_WO) {
            src = Wo + (size_t)l * D_ * D_ + (r - R_QKV);
        } else if (r < (size_t)R_QKV + R_WO + R_W1) {
            src = W1 + (size_t)l * D_ * F_ + (r - R_QKV - R_WO);
        } else if (r < LW_) {
            src = W2 + (size_t)l * F_ * D_ + (r - R_QKV - R_WO - R_W1);
        } else {
            size_t i = r - LW_;
            const float* bb = (i < D_) ? bq : (i < 2 * (size_t)D_) ? bk : bv;
            size_t ii = (i < D_) ? i : (i < 2 * (size_t)D_) ? i - D_ : i - 2 * D_;
            src = bb + (size_t)l * D_ + ii;
            is_bias = 1;
        }
        float4 v = *(const float4*)src;
        if (!is_bias) v = make_float4(rtf(v.x), rtf(v.y), rtf(v.z), rtf(v.w));
        ((float4*)g_wr)[i4] = v;
    }
}

// ---------------- tf32 tensor-core GEMM, 3-stage cp.async ----------------
// Inputs MUST be pre-rounded to tf32. C = A[M,K] @ B[K,N] + bias; flags: 1=relu, 2=round output.
#define BKG 32
#define ASTR 36
#define BSTR 136
#define STG_A (128*ASTR)
#define STG_B (BKG*BSTR)
#define STG_FL (STG_A + STG_B)
#define GSM_BYTES (3 * STG_FL * 4)

__device__ __forceinline__ void mma_tf32(float* c, const uint32_t* a, const uint32_t* b) {
    asm volatile(
        "mma.sync.aligned.m16n8k8.row.col.f32.tf32.tf32.f32 "
        "{%0,%1,%2,%3}, {%4,%5,%6,%7}, {%8,%9}, {%0,%1,%2,%3};"
        : "+f"(c[0]), "+f"(c[1]), "+f"(c[2]), "+f"(c[3])
        : "r"(a[0]), "r"(a[1]), "r"(a[2]), "r"(a[3]), "r"(b[0]), "r"(b[1]));
}

__global__ __launch_bounds__(256, 2)
void tgemm_kernel(const float* __restrict__ A, const float* __restrict__ Bm,
                  const float* __restrict__ bias, float* __restrict__ C,
                  int M, int N, int K, int flags) {
    extern __shared__ float smf[];
    const int tid = threadIdx.x;
    const int bx = blockIdx.x, by = blockIdx.y;
    const int lane = tid & 31;
    const int w = tid >> 5;
    const int lr = lane >> 2, lc = lane & 3;
    const int m0 = (w >> 2) * 64;
    const int n0 = (w & 3) * 32;

    const int am = tid >> 3;
    const int akq = tid & 7;
    const int bk = tid >> 5;
    const int bnq = tid & 31;

    const float* Ag = A + (size_t)(by * 128 + am) * K + akq * 4;
    const float* Bg = Bm + (size_t)bk * N + bx * 128 + bnq * 4;

    const int T = K >> 5;
    uint32_t sb = smem_u32(smf);

    auto load_stage = [&](int s, int t) {
        uint32_t abase = sb + (uint32_t)(s * STG_FL) * 4;
        uint32_t bbase = abase + (uint32_t)STG_A * 4;
        const float* ap = Ag + (size_t)t * BKG;
        const float* bp = Bg + (size_t)t * BKG * N;
#pragma unroll
        for (int i = 0; i < 4; i++) {
            cp16(abase + (uint32_t)((am + 32 * i) * ASTR + akq * 4) * 4,
                 ap + (size_t)(32 * i) * K);
            cp16(bbase + (uint32_t)((bk + 8 * i) * BSTR + bnq * 4) * 4,
                 bp + (size_t)(8 * i) * N);
        }
    };

    float acc[4][4][4];
#pragma unroll
    for (int i = 0; i < 4; i++)
#pragma unroll
        for (int j = 0; j < 4; j++)
#pragma unroll
            for (int r = 0; r < 4; r++) acc[i][j][r] = 0.f;

    load_stage(0, 0);
    asm volatile("cp.async.commit_group;" ::: "memory");
    if (T > 1) load_stage(1, 1);
    asm volatile("cp.async.commit_group;" ::: "memory");

    for (int t = 0; t < T; t++) {
        asm volatile("cp.async.wait_group 1;" ::: "memory");
        __syncthreads();
        if (t + 2 < T) load_stage((t + 2) % 3, t + 2);
        asm volatile("cp.async.commit_group;" ::: "memory");

        const float* As = smf + (t % 3) * STG_FL;
        const float* Bs = As + STG_A;
#pragma unroll
        for (int ks = 0; ks < 4; ks++) {
            const int kb = ks * 8;
            uint32_t afr[4][4], bfr[4][2];
#pragma unroll
            for (int mt = 0; mt < 4; mt++) {
                int r = m0 + mt * 16 + lr;
                afr[mt][0] = __float_as_uint(As[r * ASTR + kb + lc]);
                afr[mt][1] = __float_as_uint(As[(r + 8) * ASTR + kb + lc]);
                afr[mt][2] = __float_as_uint(As[r * ASTR + kb + lc + 4]);
                afr[mt][3] = __float_as_uint(As[(r + 8) * ASTR + kb + lc + 4]);
            }
#pragma unroll
            for (int nt = 0; nt < 4; nt++) {
                int n = n0 + nt * 8 + lr;
                bfr[nt][0] = __float_as_uint(Bs[(kb + lc) * BSTR + n]);
                bfr[nt][1] = __float_as_uint(Bs[(kb + lc + 4) * BSTR + n]);
            }
#pragma unroll
            for (int mt = 0; mt < 4; mt++)
#pragma unroll
                for (int nt = 0; nt < 4; nt++)
                    mma_tf32(acc[mt][nt], afr[mt], bfr[nt]);
        }
        __syncthreads();
    }

    const int relu = flags & 1, rnd = flags & 2;
#pragma unroll
    for (int nt = 0; nt < 4; nt++) {
        int col = bx * 128 + n0 + nt * 8 + 2 * lc;
        float bv0 = __ldg(&bias[col]), bv1 = __ldg(&bias[col + 1]);
#pragma unroll
        for (int mt = 0; mt < 4; mt++) {
            int row = by * 128 + m0 + mt * 16 + lr;
            float o0 = acc[mt][nt][0] + bv0;
            float o1 = acc[mt][nt][1] + bv1;
            float o2 = acc[mt][nt][2] + bv0;
            float o3 = acc[mt][nt][3] + bv1;
            if (relu) {
                o0 = fmaxf(o0, 0.f); o1 = fmaxf(o1, 0.f);
                o2 = fmaxf(o2, 0.f); o3 = fmaxf(o3, 0.f);
            }
            if (rnd) { o0 = rtf(o0); o1 = rtf(o1); o2 = rtf(o2); o3 = rtf(o3); }
            *(float2*)(C + (size_t)row * N + col)       = make_float2(o0, o1);
            *(float2*)(C + (size_t)(row + 8) * N + col) = make_float2(o2, o3);
        }
    }
}

// ================= chunked causal linear attention (packed qkv, stride QS_) =================
__device__ __forceinline__ float phi_f(float x) {
    return x > 0.f ? x + 1.f : expf(x);
}

__global__ __launch_bounds__(256)
void attn_kv_kernel(const float* __restrict__ qkv) {
    int blk = blockIdx.x;
    int bh = blk / NC, c = blk % NC;
    int b = bh / H_, h = bh % H_;
    int len = g_len[b];
    int tid = threadIdx.x;

    __shared__ float Ks[CT][DH_];
    __shared__ float Vs[CT][DH_];

    size_t kbase = ((size_t)b * S_ + (size_t)c * CT) * QS_ + D_ + h * DH_;
    size_t vbase = kbase + D_;

#pragma unroll
    for (int it = 0; it < 4; it++) {
        int idx = tid + it * 256;
        int t = idx >> 4, d4 = (idx & 15) * 4;
        float4 kv = *(const float4*)(qkv + kbase + (size_t)t * QS_ + d4);
        float4 vv = *(const float4*)(qkv + vbase + (size_t)t * QS_ + d4);
        float m = ((c * CT + t) < len) ? 1.f : 0.f;
        kv.x = phi_f(kv.x) * m; kv.y = phi_f(kv.y) * m;
        kv.z = phi_f(kv.z) * m; kv.w = phi_f(kv.w) * m;
        *(float4*)&Ks[t][d4] = kv;
        *(float4*)&Vs[t][d4] = vv;
    }
    __syncthreads();

    int d0 = (tid & 15) * 4;
    int e0 = (tid >> 4) * 4;
    float acc[4][4];
#pragma unroll
    for (int i = 0; i < 4; i++)
#pragma unroll
        for (int j = 0; j < 4; j++) acc[i][j] = 0.f;

    for (int t = 0; t < CT; t++) {
        float4 kd = *(const float4*)&Ks[t][d0];
        float4 ve = *(const float4*)&Vs[t][e0];
        float kdx[4] = {kd.x, kd.y, kd.z, kd.w};
        float vex[4] = {ve.x, ve.y, ve.z, ve.w};
#pragma unroll
        for (int i = 0; i < 4; i++)
#pragma unroll
            for (int j = 0; j < 4; j++)
                acc[i][j] = fmaf(kdx[i], vex[j], acc[i][j]);
    }

    float* Gout = g_G + ((size_t)bh * NC + c) * (DH_ * DH_);
#pragma unroll
    for (int i = 0; i < 4; i++) {
        *(float4*)&Gout[(size_t)(d0 + i) * DH_ + e0] =
            make_float4(acc[i][0], acc[i][1], acc[i][2], acc[i][3]);
    }

    if (tid < DH_) {
        float s = 0.f;
        for (int t = 0; t < CT; t++) s += Ks[t][tid];
        g_ck[((size_t)bh * NC + c) * DH_ + tid] = s;
    }
}

__global__ __launch_bounds__(256)
void attn_prefix_kernel() {
    int bh = blockIdx.x;
    int e = blockIdx.y * 256 + threadIdx.x;
    const float* G = g_G + (size_t)bh * NC * (DH_ * DH_);
    float* Sp = g_Sp + (size_t)bh * NC * (DH_ * DH_);
    float run = 0.f;
    for (int c = 0; c < NC; c++) {
        Sp[(size_t)c * (DH_ * DH_) + e] = run;
        run += G[(size_t)c * (DH_ * DH_) + e];
    }
    if (blockIdx.y == 0 && threadIdx.x < DH_) {
        int d = threadIdx.x;
        float r2 = 0.f;
        for (int c = 0; c < NC; c++) {
            g_ckp[((size_t)bh * NC + c) * DH_ + d] = r2;
            r2 += g_ck[((size_t)bh * NC + c) * DH_ + d];
        }
    }
}

#define SMP 68
__global__ __launch_bounds__(256)
void attn_out_kernel(const float* __restrict__ qkv, float* __restrict__ out) {
    extern __shared__ float sm[];
    float* Qs  = sm;
    float* Xs  = sm + 64 * SMP;
    float* As  = sm + 2 * 64 * SMP;
    float* zs  = sm + 3 * 64 * SMP;
    float* ckp = zs + 64;

    int blk = blockIdx.x;
    int bh = blk / NC, c = blk % NC;
    int b = bh / H_, h = bh % H_;
    int len = g_len[b];
    int tid = threadIdx.x;

    size_t qbase = ((size_t)b * S_ + (size_t)c * CT) * QS_ + h * DH_;
    size_t kbase = qbase + D_;
    size_t vbase = qbase + 2 * D_;
    size_t obase = ((size_t)b * S_ + (size_t)c * CT) * D_ + h * DH_;

    if (tid < DH_) ckp[tid] = g_ckp[((size_t)bh * NC + c) * DH_ + tid];

#pragma unroll
    for (int it = 0; it < 4; it++) {
        int idx = tid + it * 256;
        int t = idx >> 4, d4 = (idx & 15) * 4;
        float4 qv = *(const float4*)(qkv + qbase + (size_t)t * QS_ + d4);
        float4 kv = *(const float4*)(qkv + kbase + (size_t)t * QS_ + d4);
        qv.x = phi_f(qv.x); qv.y = phi_f(qv.y);
        qv.z = phi_f(qv.z); qv.w = phi_f(qv.w);
        float m = ((c * CT + t) < len) ? 1.f : 0.f;
        kv.x = phi_f(kv.x) * m; kv.y = phi_f(kv.y) * m;
        kv.z = phi_f(kv.z) * m; kv.w = phi_f(kv.w) * m;
        *(float4*)&Qs[t * SMP + d4] = qv;
        *(float4*)&Xs[t * SMP + d4] = kv;
    }
    __syncthreads();

    {
        int i0 = (tid >> 4) * 4;
        int j0 = (tid & 15) * 4;
        float acc[4][4];
#pragma unroll
        for (int i = 0; i < 4; i++)
#pragma unroll
            for (int j = 0; j < 4; j++) acc[i][j] = 0.f;

        for (int d = 0; d < DH_; d += 4) {
            float4 qa[4], kb[4];
#pragma unroll
            for (int i = 0; i < 4; i++) qa[i] = *(const float4*)&Qs[(i0 + i) * SMP + d];
#pragma unroll
            for (int j = 0; j < 4; j++) kb[j] = *(const float4*)&Xs[(j0 + j) * SMP + d];
#pragma unroll
            for (int i = 0; i < 4; i++)
#pragma unroll
                for (int j = 0; j < 4; j++)
                    acc[i][j] += qa[i].x * kb[j].x + qa[i].y * kb[j].y
                               + qa[i].z * kb[j].z + qa[i].w * kb[j].w;
        }
#pragma unroll
        for (int i = 0; i < 4; i++) {
            float4 row;
            row.x = (j0 + 0 <= i0 + i) ? acc[i][0] : 0.f;
            row.y = (j0 + 1 <= i0 + i) ? acc[i][1] : 0.f;
            row.z = (j0 + 2 <= i0 + i) ? acc[i][2] : 0.f;
            row.w = (j0 + 3 <= i0 + i) ? acc[i][3] : 0.f;
            *(float4*)&As[(i0 + i) * SMP + j0] = row;
        }
    }
    __syncthreads();

    if (tid < CT) {
        int i = tid;
        float z = 0.f;
        for (int j = 0; j < CT; j++) z += As[i * SMP + j];
        for (int d = 0; d < DH_; d++) z += Qs[i * SMP + d] * ckp[d];
        zs[i] = z;
    }
#pragma unroll
    for (int it = 0; it < 4; it++) {
        int idx = tid + it * 256;
        int t = idx >> 4, d4 = (idx & 15) * 4;
        float4 vv = *(const float4*)(qkv + vbase + (size_t)t * QS_ + d4);
        *(float4*)&Xs[t * SMP + d4] = vv;
    }
    __syncthreads();

    int i0 = (tid >> 4) * 4;
    int e0 = (tid & 15) * 4;
    float acc2[4][4];
#pragma unroll
    for (int i = 0; i < 4; i++)
#pragma unroll
        for (int j = 0; j < 4; j++) acc2[i][j] = 0.f;

    for (int j = 0; j < CT; j++) {
        float a0 = As[(i0 + 0) * SMP + j];
        float a1 = As[(i0 + 1) * SMP + j];
        float a2 = As[(i0 + 2) * SMP + j];
        float a3 = As[(i0 + 3) * SMP + j];
        float4 vj = *(const float4*)&Xs[j * SMP + e0];
        acc2[0][0] = fmaf(a0, vj.x, acc2[0][0]); acc2[0][1] = fmaf(a0, vj.y, acc2[0][1]);
        acc2[0][2] = fmaf(a0, vj.z, acc2[0][2]); acc2[0][3] = fmaf(a0, vj.w, acc2[0][3]);
        acc2[1][0] = fmaf(a1, vj.x, acc2[1][0]); acc2[1][1] = fmaf(a1, vj.y, acc2[1][1]);
        acc2[1][2] = fmaf(a1, vj.z, acc2[1][2]); acc2[1][3] = fmaf(a1, vj.w, acc2[1][3]);
        acc2[2][0] = fmaf(a2, vj.x, acc2[2][0]); acc2[2][1] = fmaf(a2, vj.y, acc2[2][1]);
        acc2[2][2] = fmaf(a2, vj.z, acc2[2][2]); acc2[2][3] = fmaf(a2, vj.w, acc2[2][3]);
        acc2[3][0] = fmaf(a3, vj.x, acc2[3][0]); acc2[3][1] = fmaf(a3, vj.y, acc2[3][1]);
        acc2[3][2] = fmaf(a3, vj.z, acc2[3][2]); acc2[3][3] = fmaf(a3, vj.w, acc2[3][3]);
    }
    __syncthreads();

    {
        const float* Sp = g_Sp + ((size_t)bh * NC + c) * (DH_ * DH_);
#pragma unroll
        for (int it = 0; it < 4; it++) {
            int idx = tid + it * 256;
            int d = idx >> 4, e4 = (idx & 15) * 4;
            float4 sv = *(const float4*)(Sp + (size_t)d * DH_ + e4);
            *(float4*)&As[d * SMP + e4] = sv;
        }
    }
    __syncthreads();

    for (int d = 0; d < DH_; d++) {
        float q0 = Qs[(i0 + 0) * SMP + d];
        float q1 = Qs[(i0 + 1) * SMP + d];
        float q2 = Qs[(i0 + 2) * SMP + d];
        float q3 = Qs[(i0 + 3) * SMP + d];
        float4 sd = *(const float4*)&As[d * SMP + e0];
        acc2[0][0] = fmaf(q0, sd.x, acc2[0][0]); acc2[0][1] = fmaf(q0, sd.y, acc2[0][1]);
        acc2[0][2] = fmaf(q0, sd.z, acc2[0][2]); acc2[0][3] = fmaf(q0, sd.w, acc2[0][3]);
        acc2[1][0] = fmaf(q1, sd.x, acc2[1][0]); acc2[1][1] = fmaf(q1, sd.y, acc2[1][1]);
        acc2[1][2] = fmaf(q1, sd.z, acc2[1][2]); acc2[1][3] = fmaf(q1, sd.w, acc2[1][3]);
        acc2[2][0] = fmaf(q2, sd.x, acc2[2][0]); acc2[2][1] = fmaf(q2, sd.y, acc2[2][1]);
        acc2[2][2] = fmaf(q2, sd.z, acc2[2][2]); acc2[2][3] = fmaf(q2, sd.w, acc2[2][3]);
        acc2[3][0] = fmaf(q3, sd.x, acc2[3][0]); acc2[3][1] = fmaf(q3, sd.y, acc2[3][1]);
        acc2[3][2] = fmaf(q3, sd.z, acc2[3][2]); acc2[3][3] = fmaf(q3, sd.w, acc2[3][3]);
    }

#pragma unroll
    for (int i = 0; i < 4; i++) {
        float inv = 1.f / (zs[i0 + i] + EPS_);
        float4 o;
        o.x = rtf(acc2[i][0] * inv); o.y = rtf(acc2[i][1] * inv);
        o.z = rtf(acc2[i][2] * inv); o.w = rtf(acc2[i][3] * inv);
        *(float4*)(out + obase + (size_t)(i0 + i) * D_ + e0) = o;
    }
}
#define SM3_BYTES ((3*64*SMP + 128) * 4)

// ---------------- residual + layernorm (writes exact + optional rounded) ----------------
__global__ __launch_bounds__(128)
void ln_kernel(const float* __restrict__ base, const float* __restrict__ delta,
               const float* __restrict__ gam, const float* __restrict__ bet,
               float* __restrict__ out, float* __restrict__ out_r) {
    int row = blockIdx.x;
    int tid = threadIdx.x;
    float4 x4 = ((const float4*)(base + (size_t)row * D_))[tid];
    if (delta != nullptr) {
        float4 d4 = ((const float4*)(delta + (size_t)row * D_))[tid];
        x4.x += d4.x; x4.y += d4.y; x4.z += d4.z; x4.w += d4.w;
    }
    float s  = x4.x + x4.y + x4.z + x4.w;
    float ss = x4.x * x4.x + x4.y * x4.y + x4.z * x4.z + x4.w * x4.w;
#pragma unroll
    for (int o = 16; o > 0; o >>= 1) {
        s  += __shfl_xor_sync(0xffffffffu, s, o);
        ss += __shfl_xor_sync(0xffffffffu, ss, o);
    }
    __shared__ float s1[4], s2[4];
    int wid = tid >> 5;
    if ((tid & 31) == 0) { s1[wid] = s; s2[wid] = ss; }
    __syncthreads();
    s  = s1[0] + s1[1] + s1[2] + s1[3];
    ss = s2[0] + s2[1] + s2[2] + s2[3];
    float mu  = s * (1.f / D_);
    float var = ss * (1.f / D_) - mu * mu;
    float rstd = rsqrtf(var + LN_EPS_);
    float4 g4 = ((const float4*)gam)[tid];
    float4 b4 = ((const float4*)bet)[tid];
    float4 o4;
    o4.x = (x4.x - mu) * rstd * g4.x + b4.x;
    o4.y = (x4.y - mu) * rstd * g4.y + b4.y;
    o4.z = (x4.z - mu) * rstd * g4.z + b4.z;
    o4.w = (x4.w - mu) * rstd * g4.w + b4.w;
    ((float4*)(out + (size_t)row * D_))[tid] = o4;
    if (out_r != nullptr)
        ((float4*)(out_r + (size_t)row * D_))[tid] =
            make_float4(rtf(o4.x), rtf(o4.y), rtf(o4.z), rtf(o4.w));
}

// ---------------- driver ----------------
extern "C" void kernel_launch(void* const* d_in, const int* in_sizes, int n_in,
                              void* d_out, int out_size) {
    const int*   x   = (const int*)  d_in[0];
    const float* emb = (const float*)d_in[1];
    const float* pe  = (const float*)d_in[2];
    const float* Wq  = (const float*)d_in[3];
    const float* bq  = (const float*)d_in[4];
    const float* Wk  = (const float*)d_in[5];
    const float* bk  = (const float*)d_in[6];
    const float* Wv  = (const float*)d_in[7];
    const float* bv  = (const float*)d_in[8];
    const float* Wo  = (const float*)d_in[9];
    const float* bo  = (const float*)d_in[10];
    const float* W1  = (const float*)d_in[11];
    const float* b1  = (const float*)d_in[12];
    const float* W2  = (const float*)d_in[13];
    const float* b2  = (const float*)d_in[14];
    const float* g1  = (const float*)d_in[15];
    const float* be1 = (const float*)d_in[16];
    const float* g2  = (const float*)d_in[17];
    const float* be2 = (const float*)d_in[18];
    const float* gf  = (const float*)d_in[19];
    const float* bf  = (const float*)d_in[20];
    float* out = (float*)d_out;

    float *p_h, *p_hr, *p_qkv, *p_attn, *p_tmp, *p_ffn, *p_wr;
    cudaGetSymbolAddress((void**)&p_h,    g_h);
    cudaGetSymbolAddress((void**)&p_hr,   g_hr);
    cudaGetSymbolAddress((void**)&p_qkv,  g_qkv);
    cudaGetSymbolAddress((void**)&p_attn, g_attn);
    cudaGetSymbolAddress((void**)&p_tmp,  g_tmp);
    cudaGetSymbolAddress((void**)&p_ffn,  g_ffn);
    cudaGetSymbolAddress((void**)&p_wr,   g_wr);

    cudaFuncSetAttribute(attn_out_kernel,
                         cudaFuncAttributeMaxDynamicSharedMemorySize, SM3_BYTES);
    cudaFuncSetAttribute(tgemm_kernel,
                         cudaFuncAttributeMaxDynamicSharedMemorySize, GSM_BYTES);

    lengths_kernel<<<B_, 256>>>(x);
    embed_kernel<<<BS_, 128>>>(x, emb, pe);
    pack_kernel<<<2048, 256>>>(Wq, Wk, Wv, Wo, W1, W2, bq, bk, bv);

    dim3 gQ(QS_ / 128, BS_ / 128);  // (12, 64)
    dim3 gD(D_ / 128, BS_ / 128);   // (4, 64)
    dim3 gF(F_ / 128, BS_ / 128);   // (16, 64)

    for (int l = 0; l < NL_; l++) {
        const float* wqkv = p_wr + (size_t)l * LWP_;
        const float* wo   = wqkv + R_QKV;
        const float* w1   = wo + R_WO;
        const float* w2   = w1 + R_W1;
        const float* bqkv = wqkv + LW_;
        const float* bo_l = bo + (size_t)l * D_;
        const float* b1_l = b1 + (size_t)l * F_;
        const float* b2_l = b2 + (size_t)l * D_;

        tgemm_kernel<<<gQ, 256, GSM_BYTES>>>(p_hr, wqkv, bqkv, p_qkv, BS_, QS_, D_, 0);

        attn_kv_kernel<<<BH * NC, 256>>>(p_qkv);
        attn_prefix_kernel<<<dim3(BH, 16), 256>>>();
        attn_out_kernel<<<BH * NC, 256, SM3_BYTES>>>(p_qkv, p_attn);

        tgemm_kernel<<<gD, 256, GSM_BYTES>>>(p_attn, wo, bo_l, p_tmp, BS_, D_, D_, 0);
        ln_kernel<<<BS_, 128>>>(p_h, p_tmp, g1 + (size_t)l * D_, be1 + (size_t)l * D_, p_h, p_hr);

        tgemm_kernel<<<gF, 256, GSM_BYTES>>>(p_hr, w1, b1_l, p_ffn, BS_, F_, D_, 1 | 2);
        tgemm_kernel<<<gD, 256, GSM_BYTES>>>(p_ffn, w2, b2_l, p_tmp, BS_, D_, F_, 0);
        ln_kernel<<<BS_, 128>>>(p_h, p_tmp, g2 + (size_t)l * D_, be2 + (size_t)l * D_, p_h, p_hr);
    }

    ln_kernel<<<BS_, 128>>>(p_h, nullptr, gf, bf, out, nullptr);
    (void)in_sizes; (void)n_in; (void)out_size;
}

// round 10
// speedup vs baseline: 3.8162x; 1.0044x over previous
#include <cuda_runtime.h>
#include <cuda_bf16.h>
#include <stdint.h>
#include <math.h>

#define B_  4
#define S_  2048
#define D_  512
#define H_  8
#define DH_ 64
#define F_  2048
#define NL_ 4
#define BS_ (B_*S_)          // 8192 rows
#define EPS_    1e-6f
#define LN_EPS_ 1e-5f

#define CT  64               // attention chunk length
#define NC  (S_/CT)          // 32 chunks
#define BH  (B_*H_)          // 32 batch-heads
#define QS_ 1536             // packed qkv row stride

// packed per-layer layout: [Wqkv 512x1536][Wo 512x512][W1 512x2048][W2 2048x512][bqkv 1536]
#define R_QKV  (D_*3*D_)
#define R_WO   (D_*D_)
#define R_W1   (D_*F_)
#define R_W2   (F_*D_)
#define LW_    ((size_t)R_QKV + R_WO + R_W1 + R_W2)
#define LWP_   (LW_ + QS_)

// ---------------- scratch (device globals; no allocation allowed) ----------------
__device__ float g_h   [BS_*D_];
__device__ float g_hr  [BS_*D_];
__device__ float g_qkv [(size_t)BS_*QS_];
__device__ float g_attn[BS_*D_];
__device__ float g_tmp [BS_*D_];
__device__ float g_ffn [BS_*F_];
__device__ float g_wr  [NL_*LWP_];
__device__ float g_G   [(size_t)BH*NC*DH_*DH_];
__device__ float g_Sp  [(size_t)BH*NC*DH_*DH_];
__device__ float g_ck  [BH*NC*DH_];
__device__ float g_ckp [BH*NC*DH_];
__device__ int   g_len [B_];

__device__ __forceinline__ uint32_t f2tf(float f) {
    uint32_t u;
    asm("cvt.rna.tf32.f32 %0, %1;" : "=r"(u) : "f"(f));
    return u;
}
__device__ __forceinline__ float rtf(float f) { return __uint_as_float(f2tf(f)); }

__device__ __forceinline__ uint32_t smem_u32(const void* p) {
    uint32_t a;
    asm("{ .reg .u64 t; cvta.to.shared.u64 t, %1; cvt.u32.u64 %0, t; }" : "=r"(a) : "l"(p));
    return a;
}
__device__ __forceinline__ void cp16(uint32_t dst, const void* src) {
    asm volatile("cp.async.cg.shared.global [%0], [%1], 16;" :: "r"(dst), "l"(src));
}

// ---------------- lengths ----------------
__global__ void lengths_kernel(const int* __restrict__ x) {
    int b = blockIdx.x;
    int tid = threadIdx.x;
    __shared__ int sred[256];
    int cnt = 0;
    for (int s = tid; s < S_; s += 256) cnt += (x[b * S_ + s] != 0) ? 1 : 0;
    sred[tid] = cnt;
    __syncthreads();
    for (int o = 128; o > 0; o >>= 1) {
        if (tid < o) sred[tid] += sred[tid + o];
        __syncthreads();
    }
    if (tid == 0) g_len[b] = sred[0];
}

// ---------------- embedding + positional encoding ----------------
__global__ void embed_kernel(const int* __restrict__ x,
                             const float* __restrict__ emb,
                             const float* __restrict__ pe) {
    int row = blockIdx.x;
    int s = row % S_;
    int tok = x[row];
    const float4* e4 = (const float4*)(emb + (size_t)tok * D_);
    const float4* p4 = (const float4*)(pe + (size_t)s * D_);
    int i = threadIdx.x;
    float4 a = e4[i], p = p4[i];
    float4 o = make_float4(a.x + p.x, a.y + p.y, a.z + p.z, a.w + p.w);
    ((float4*)(g_h + (size_t)row * D_))[i] = o;
    ((float4*)(g_hr + (size_t)row * D_))[i] =
        make_float4(rtf(o.x), rtf(o.y), rtf(o.z), rtf(o.w));
}

// ---------------- pack: round + lay out all weights (one launch) ----------------
__global__ void pack_kernel(const float* __restrict__ Wq, const float* __restrict__ Wk,
                            const float* __restrict__ Wv, const float* __restrict__ Wo,
                            const float* __restrict__ W1, const float* __restrict__ W2,
                            const float* __restrict__ bq, const float* __restrict__ bk,
                            const float* __restrict__ bv) {
    const size_t total4 = (size_t)NL_ * LWP_ / 4;
    for (size_t i4 = (size_t)blockIdx.x * blockDim.x + threadIdx.x; i4 < total4;
         i4 += (size_t)gridDim.x * blockDim.x) {
        size_t e = i4 * 4;
        int l = (int)(e / LWP_);
        size_t r = e % LWP_;
        const float* src;
        int is_bias = 0;
        if (r < R_QKV) {
            int k = (int)(r / QS_), n = (int)(r % QS_);
            const float* W = (n < D_) ? Wq : (n < 2 * D_) ? Wk : Wv;
            int nn = (n < D_) ? n : (n < 2 * D_) ? n - D_ : n - 2 * D_;
            src = W + (size_t)l * D_ * D_ + (size_t)k * D_ + nn;
        } else if (r < (size_t)R_QKV + R_WO) {
            src = Wo + (size_t)l * D_ * D_ + (r - R_QKV);
        } else if (r < (size_t)R_QKV + R_WO + R_W1) {
            src = W1 + (size_t)l * D_ * F_ + (r - R_QKV - R_WO);
        } else if (r < LW_) {
            src = W2 + (size_t)l * F_ * D_ + (r - R_QKV - R_WO - R_W1);
        } else {
            size_t i = r - LW_;
            const float* bb = (i < D_) ? bq : (i < 2 * (size_t)D_) ? bk : bv;
            size_t ii = (i < D_) ? i : (i < 2 * (size_t)D_) ? i - D_ : i - 2 * D_;
            src = bb + (size_t)l * D_ + ii;
            is_bias = 1;
        }
        float4 v = *(const float4*)src;
        if (!is_bias) v = make_float4(rtf(v.x), rtf(v.y), rtf(v.z), rtf(v.w));
        ((float4*)g_wr)[i4] = v;
    }
}

// ---------------- tf32 tensor-core GEMM, 128x256 tile, 3-stage cp.async ----------------
// Inputs pre-rounded to tf32. C = A[M,K] @ B[K,N] + bias; flags: 1=relu, 2=round output.
// 8 warps (2m x 4n), warp tile 64x64. N % 256 == 0.
#define BKG 32
#define ASTR 36     // banks (4*lr+lc) — conflict-free
#define BSTR 264    // banks (8*lc+lr) — conflict-free
#define STG_A (128*ASTR)
#define STG_B (BKG*BSTR)
#define STG_FL (STG_A + STG_B)            // 13056 floats
#define GSM_BYTES (3 * STG_FL * 4)        // 156672 B

__device__ __forceinline__ void mma_tf32(float* c, const uint32_t* a, const uint32_t* b) {
    asm volatile(
        "mma.sync.aligned.m16n8k8.row.col.f32.tf32.tf32.f32 "
        "{%0,%1,%2,%3}, {%4,%5,%6,%7}, {%8,%9}, {%0,%1,%2,%3};"
        : "+f"(c[0]), "+f"(c[1]), "+f"(c[2]), "+f"(c[3])
        : "r"(a[0]), "r"(a[1]), "r"(a[2]), "r"(a[3]), "r"(b[0]), "r"(b[1]));
}

__global__ __launch_bounds__(256, 1)
void tgemm_kernel(const float* __restrict__ A, const float* __restrict__ Bm,
                  const float* __restrict__ bias, float* __restrict__ C,
                  int M, int N, int K, int flags) {
    extern __shared__ float smf[];
    const int tid = threadIdx.x;
    const int bx = blockIdx.x, by = blockIdx.y;
    const int lane = tid & 31;
    const int w = tid >> 5;
    const int lr = lane >> 2, lc = lane & 3;
    const int m0 = (w >> 2) * 64;     // 0 or 64
    const int n0 = (w & 3) * 64;      // 0,64,128,192

    const int am = tid >> 3;          // 0..31 (+32*i)
    const int akq = tid & 7;
    const int bk = tid >> 5;          // 0..7 (+8*i)
    const int bnq = tid & 31;         // 16B chunk (+32 for second half)

    const float* Ag = A + (size_t)(by * 128 + am) * K + akq * 4;
    const float* Bg = Bm + (size_t)bk * N + bx * 256 + bnq * 4;

    const int T = K >> 5;
    uint32_t sb = smem_u32(smf);

    auto load_stage = [&](int s, int t) {
        uint32_t abase = sb + (uint32_t)(s * STG_FL) * 4;
        uint32_t bbase = abase + (uint32_t)STG_A * 4;
        const float* ap = Ag + (size_t)t * BKG;
        const float* bp = Bg + (size_t)t * BKG * N;
#pragma unroll
        for (int i = 0; i < 4; i++) {
            cp16(abase + (uint32_t)((am + 32 * i) * ASTR + akq * 4) * 4,
                 ap + (size_t)(32 * i) * K);
            cp16(bbase + (uint32_t)((bk + 8 * i) * BSTR + bnq * 4) * 4,
                 bp + (size_t)(8 * i) * N);
            cp16(bbase + (uint32_t)((bk + 8 * i) * BSTR + bnq * 4 + 128) * 4,
                 bp + (size_t)(8 * i) * N + 128);
        }
    };

    float acc[4][8][4];
#pragma unroll
    for (int i = 0; i < 4; i++)
#pragma unroll
        for (int j = 0; j < 8; j++)
#pragma unroll
            for (int r = 0; r < 4; r++) acc[i][j][r] = 0.f;

    load_stage(0, 0);
    asm volatile("cp.async.commit_group;" ::: "memory");
    if (T > 1) load_stage(1, 1);
    asm volatile("cp.async.commit_group;" ::: "memory");

    for (int t = 0; t < T; t++) {
        asm volatile("cp.async.wait_group 1;" ::: "memory");
        __syncthreads();
        if (t + 2 < T) load_stage((t + 2) % 3, t + 2);
        asm volatile("cp.async.commit_group;" ::: "memory");

        const float* As = smf + (t % 3) * STG_FL;
        const float* Bs = As + STG_A;
#pragma unroll
        for (int ks = 0; ks < 4; ks++) {
            const int kb = ks * 8;
            uint32_t afr[4][4], bfr[8][2];
#pragma unroll
            for (int mt = 0; mt < 4; mt++) {
                int r = m0 + mt * 16 + lr;
                afr[mt][0] = __float_as_uint(As[r * ASTR + kb + lc]);
                afr[mt][1] = __float_as_uint(As[(r + 8) * ASTR + kb + lc]);
                afr[mt][2] = __float_as_uint(As[r * ASTR + kb + lc + 4]);
                afr[mt][3] = __float_as_uint(As[(r + 8) * ASTR + kb + lc + 4]);
            }
#pragma unroll
            for (int nt = 0; nt < 8; nt++) {
                int n = n0 + nt * 8 + lr;
                bfr[nt][0] = __float_as_uint(Bs[(kb + lc) * BSTR + n]);
                bfr[nt][1] = __float_as_uint(Bs[(kb + lc + 4) * BSTR + n]);
            }
#pragma unroll
            for (int mt = 0; mt < 4; mt++)
#pragma unroll
                for (int nt = 0; nt < 8; nt++)
                    mma_tf32(acc[mt][nt], afr[mt], bfr[nt]);
        }
        __syncthreads();
    }

    const int relu = flags & 1, rnd = flags & 2;
#pragma unroll
    for (int nt = 0; nt < 8; nt++) {
        int col = bx * 256 + n0 + nt * 8 + 2 * lc;
        float bv0 = __ldg(&bias[col]), bv1 = __ldg(&bias[col + 1]);
#pragma unroll
        for (int mt = 0; mt < 4; mt++) {
            int row = by * 128 + m0 + mt * 16 + lr;
            float o0 = acc[mt][nt][0] + bv0;
            float o1 = acc[mt][nt][1] + bv1;
            float o2 = acc[mt][nt][2] + bv0;
            float o3 = acc[mt][nt][3] + bv1;
            if (relu) {
                o0 = fmaxf(o0, 0.f); o1 = fmaxf(o1, 0.f);
                o2 = fmaxf(o2, 0.f); o3 = fmaxf(o3, 0.f);
            }
            if (rnd) { o0 = rtf(o0); o1 = rtf(o1); o2 = rtf(o2); o3 = rtf(o3); }
            *(float2*)(C + (size_t)row * N + col)       = make_float2(o0, o1);
            *(float2*)(C + (size_t)(row + 8) * N + col) = make_float2(o2, o3);
        }
    }
}

// ================= chunked causal linear attention (packed qkv, stride QS_) =================
__device__ __forceinline__ float phi_f(float x) {
    return x > 0.f ? x + 1.f : expf(x);
}

__global__ __launch_bounds__(256)
void attn_kv_kernel(const float* __restrict__ qkv) {
    int blk = blockIdx.x;
    int bh = blk / NC, c = blk % NC;
    int b = bh / H_, h = bh % H_;
    int len = g_len[b];
    int tid = threadIdx.x;

    __shared__ float Ks[CT][DH_];
    __shared__ float Vs[CT][DH_];

    size_t kbase = ((size_t)b * S_ + (size_t)c * CT) * QS_ + D_ + h * DH_;
    size_t vbase = kbase + D_;

#pragma unroll
    for (int it = 0; it < 4; it++) {
        int idx = tid + it * 256;
        int t = idx >> 4, d4 = (idx & 15) * 4;
        float4 kv = *(const float4*)(qkv + kbase + (size_t)t * QS_ + d4);
        float4 vv = *(const float4*)(qkv + vbase + (size_t)t * QS_ + d4);
        float m = ((c * CT + t) < len) ? 1.f : 0.f;
        kv.x = phi_f(kv.x) * m; kv.y = phi_f(kv.y) * m;
        kv.z = phi_f(kv.z) * m; kv.w = phi_f(kv.w) * m;
        *(float4*)&Ks[t][d4] = kv;
        *(float4*)&Vs[t][d4] = vv;
    }
    __syncthreads();

    int d0 = (tid & 15) * 4;
    int e0 = (tid >> 4) * 4;
    float acc[4][4];
#pragma unroll
    for (int i = 0; i < 4; i++)
#pragma unroll
        for (int j = 0; j < 4; j++) acc[i][j] = 0.f;

    for (int t = 0; t < CT; t++) {
        float4 kd = *(const float4*)&Ks[t][d0];
        float4 ve = *(const float4*)&Vs[t][e0];
        float kdx[4] = {kd.x, kd.y, kd.z, kd.w};
        float vex[4] = {ve.x, ve.y, ve.z, ve.w};
#pragma unroll
        for (int i = 0; i < 4; i++)
#pragma unroll
            for (int j = 0; j < 4; j++)
                acc[i][j] = fmaf(kdx[i], vex[j], acc[i][j]);
    }

    float* Gout = g_G + ((size_t)bh * NC + c) * (DH_ * DH_);
#pragma unroll
    for (int i = 0; i < 4; i++) {
        *(float4*)&Gout[(size_t)(d0 + i) * DH_ + e0] =
            make_float4(acc[i][0], acc[i][1], acc[i][2], acc[i][3]);
    }

    if (tid < DH_) {
        float s = 0.f;
        for (int t = 0; t < CT; t++) s += Ks[t][tid];
        g_ck[((size_t)bh * NC + c) * DH_ + tid] = s;
    }
}

__global__ __launch_bounds__(256)
void attn_prefix_kernel() {
    int bh = blockIdx.x;
    int e = blockIdx.y * 256 + threadIdx.x;
    const float* G = g_G + (size_t)bh * NC * (DH_ * DH_);
    float* Sp = g_Sp + (size_t)bh * NC * (DH_ * DH_);
    float run = 0.f;
    for (int c = 0; c < NC; c++) {
        Sp[(size_t)c * (DH_ * DH_) + e] = run;
        run += G[(size_t)c * (DH_ * DH_) + e];
    }
    if (blockIdx.y == 0 && threadIdx.x < DH_) {
        int d = threadIdx.x;
        float r2 = 0.f;
        for (int c = 0; c < NC; c++) {
            g_ckp[((size_t)bh * NC + c) * DH_ + d] = r2;
            r2 += g_ck[((size_t)bh * NC + c) * DH_ + d];
        }
    }
}

#define SMP 68
__global__ __launch_bounds__(256)
void attn_out_kernel(const float* __restrict__ qkv, float* __restrict__ out) {
    extern __shared__ float sm[];
    float* Qs  = sm;
    float* Xs  = sm + 64 * SMP;
    float* As  = sm + 2 * 64 * SMP;
    float* zs  = sm + 3 * 64 * SMP;
    float* ckp = zs + 64;

    int blk = blockIdx.x;
    int bh = blk / NC, c = blk % NC;
    int b = bh / H_, h = bh % H_;
    int len = g_len[b];
    int tid = threadIdx.x;

    size_t qbase = ((size_t)b * S_ + (size_t)c * CT) * QS_ + h * DH_;
    size_t kbase = qbase + D_;
    size_t vbase = qbase + 2 * D_;
    size_t obase = ((size_t)b * S_ + (size_t)c * CT) * D_ + h * DH_;

    if (tid < DH_) ckp[tid] = g_ckp[((size_t)bh * NC + c) * DH_ + tid];

#pragma unroll
    for (int it = 0; it < 4; it++) {
        int idx = tid + it * 256;
        int t = idx >> 4, d4 = (idx & 15) * 4;
        float4 qv = *(const float4*)(qkv + qbase + (size_t)t * QS_ + d4);
        float4 kv = *(const float4*)(qkv + kbase + (size_t)t * QS_ + d4);
        qv.x = phi_f(qv.x); qv.y = phi_f(qv.y);
        qv.z = phi_f(qv.z); qv.w = phi_f(qv.w);
        float m = ((c * CT + t) < len) ? 1.f : 0.f;
        kv.x = phi_f(kv.x) * m; kv.y = phi_f(kv.y) * m;
        kv.z = phi_f(kv.z) * m; kv.w = phi_f(kv.w) * m;
        *(float4*)&Qs[t * SMP + d4] = qv;
        *(float4*)&Xs[t * SMP + d4] = kv;
    }
    __syncthreads();

    {
        int i0 = (tid >> 4) * 4;
        int j0 = (tid & 15) * 4;
        float acc[4][4];
#pragma unroll
        for (int i = 0; i < 4; i++)
#pragma unroll
            for (int j = 0; j < 4; j++) acc[i][j] = 0.f;

        for (int d = 0; d < DH_; d += 4) {
            float4 qa[4], kb[4];
#pragma unroll
            for (int i = 0; i < 4; i++) qa[i] = *(const float4*)&Qs[(i0 + i) * SMP + d];
#pragma unroll
            for (int j = 0; j < 4; j++) kb[j] = *(const float4*)&Xs[(j0 + j) * SMP + d];
#pragma unroll
            for (int i = 0; i < 4; i++)
#pragma unroll
                for (int j = 0; j < 4; j++)
                    acc[i][j] += qa[i].x * kb[j].x + qa[i].y * kb[j].y
                               + qa[i].z * kb[j].z + qa[i].w * kb[j].w;
        }
#pragma unroll
        for (int i = 0; i < 4; i++) {
            float4 row;
            row.x = (j0 + 0 <= i0 + i) ? acc[i][0] : 0.f;
            row.y = (j0 + 1 <= i0 + i) ? acc[i][1] : 0.f;
            row.z = (j0 + 2 <= i0 + i) ? acc[i][2] : 0.f;
            row.w = (j0 + 3 <= i0 + i) ? acc[i][3] : 0.f;
            *(float4*)&As[(i0 + i) * SMP + j0] = row;
        }
    }
    __syncthreads();

    if (tid < CT) {
        int i = tid;
        float z = 0.f;
        for (int j = 0; j < CT; j++) z += As[i * SMP + j];
        for (int d = 0; d < DH_; d++) z += Qs[i * SMP + d] * ckp[d];
        zs[i] = z;
    }
#pragma unroll
    for (int it = 0; it < 4; it++) {
        int idx = tid + it * 256;
        int t = idx >> 4, d4 = (idx & 15) * 4;
        float4 vv = *(const float4*)(qkv + vbase + (size_t)t * QS_ + d4);
        *(float4*)&Xs[t * SMP + d4] = vv;
    }
    __syncthreads();

    int i0 = (tid >> 4) * 4;
    int e0 = (tid & 15) * 4;
    float acc2[4][4];
#pragma unroll
    for (int i = 0; i < 4; i++)
#pragma unroll
        for (int j = 0; j < 4; j++) acc2[i][j] = 0.f;

    for (int j = 0; j < CT; j++) {
        float a0 = As[(i0 + 0) * SMP + j];
        float a1 = As[(i0 + 1) * SMP + j];
        float a2 = As[(i0 + 2) * SMP + j];
        float a3 = As[(i0 + 3) * SMP + j];
        float4 vj = *(const float4*)&Xs[j * SMP + e0];
        acc2[0][0] = fmaf(a0, vj.x, acc2[0][0]); acc2[0][1] = fmaf(a0, vj.y, acc2[0][1]);
        acc2[0][2] = fmaf(a0, vj.z, acc2[0][2]); acc2[0][3] = fmaf(a0, vj.w, acc2[0][3]);
        acc2[1][0] = fmaf(a1, vj.x, acc2[1][0]); acc2[1][1] = fmaf(a1, vj.y, acc2[1][1]);
        acc2[1][2] = fmaf(a1, vj.z, acc2[1][2]); acc2[1][3] = fmaf(a1, vj.w, acc2[1][3]);
        acc2[2][0] = fmaf(a2, vj.x, acc2[2][0]); acc2[2][1] = fmaf(a2, vj.y, acc2[2][1]);
        acc2[2][2] = fmaf(a2, vj.z, acc2[2][2]); acc2[2][3] = fmaf(a2, vj.w, acc2[2][3]);
        acc2[3][0] = fmaf(a3, vj.x, acc2[3][0]); acc2[3][1] = fmaf(a3, vj.y, acc2[3][1]);
        acc2[3][2] = fmaf(a3, vj.z, acc2[3][2]); acc2[3][3] = fmaf(a3, vj.w, acc2[3][3]);
    }
    __syncthreads();

    {
        const float* Sp = g_Sp + ((size_t)bh * NC + c) * (DH_ * DH_);
#pragma unroll
        for (int it = 0; it < 4; it++) {
            int idx = tid + it * 256;
            int d = idx >> 4, e4 = (idx & 15) * 4;
            float4 sv = *(const float4*)(Sp + (size_t)d * DH_ + e4);
            *(float4*)&As[d * SMP + e4] = sv;
        }
    }
    __syncthreads();

    for (int d = 0; d < DH_; d++) {
        float q0 = Qs[(i0 + 0) * SMP + d];
        float q1 = Qs[(i0 + 1) * SMP + d];
        float q2 = Qs[(i0 + 2) * SMP + d];
        float q3 = Qs[(i0 + 3) * SMP + d];
        float4 sd = *(const float4*)&As[d * SMP + e0];
        acc2[0][0] = fmaf(q0, sd.x, acc2[0][0]); acc2[0][1] = fmaf(q0, sd.y, acc2[0][1]);
        acc2[0][2] = fmaf(q0, sd.z, acc2[0][2]); acc2[0][3] = fmaf(q0, sd.w, acc2[0][3]);
        acc2[1][0] = fmaf(q1, sd.x, acc2[1][0]); acc2[1][1] = fmaf(q1, sd.y, acc2[1][1]);
        acc2[1][2] = fmaf(q1, sd.z, acc2[1][2]); acc2[1][3] = fmaf(q1, sd.w, acc2[1][3]);
        acc2[2][0] = fmaf(q2, sd.x, acc2[2][0]); acc2[2][1] = fmaf(q2, sd.y, acc2[2][1]);
        acc2[2][2] = fmaf(q2, sd.z, acc2[2][2]); acc2[2][3] = fmaf(q2, sd.w, acc2[2][3]);
        acc2[3][0] = fmaf(q3, sd.x, acc2[3][0]); acc2[3][1] = fmaf(q3, sd.y, acc2[3][1]);
        acc2[3][2] = fmaf(q3, sd.z, acc2[3][2]); acc2[3][3] = fmaf(q3, sd.w, acc2[3][3]);
    }

#pragma unroll
    for (int i = 0; i < 4; i++) {
        float inv = 1.f / (zs[i0 + i] + EPS_);
        float4 o;
        o.x = rtf(acc2[i][0] * inv); o.y = rtf(acc2[i][1] * inv);
        o.z = rtf(acc2[i][2] * inv); o.w = rtf(acc2[i][3] * inv);
        *(float4*)(out + obase + (size_t)(i0 + i) * D_ + e0) = o;
    }
}
#define SM3_BYTES ((3*64*SMP + 128) * 4)

// ---------------- residual + layernorm ----------------
__global__ __launch_bounds__(128)
void ln_kernel(const float* __restrict__ base, const float* __restrict__ delta,
               const float* __restrict__ gam, const float* __restrict__ bet,
               float* __restrict__ out, float* __restrict__ out_r) {
    int row = blockIdx.x;
    int tid = threadIdx.x;
    float4 x4 = ((const float4*)(base + (size_t)row * D_))[tid];
    if (delta != nullptr) {
        float4 d4 = ((const float4*)(delta + (size_t)row * D_))[tid];
        x4.x += d4.x; x4.y += d4.y; x4.z += d4.z; x4.w += d4.w;
    }
    float s  = x4.x + x4.y + x4.z + x4.w;
    float ss = x4.x * x4.x + x4.y * x4.y + x4.z * x4.z + x4.w * x4.w;
#pragma unroll
    for (int o = 16; o > 0; o >>= 1) {
        s  += __shfl_xor_sync(0xffffffffu, s, o);
        ss += __shfl_xor_sync(0xffffffffu, ss, o);
    }
    __shared__ float s1[4], s2[4];
    int wid = tid >> 5;
    if ((tid & 31) == 0) { s1[wid] = s; s2[wid] = ss; }
    __syncthreads();
    s  = s1[0] + s1[1] + s1[2] + s1[3];
    ss = s2[0] + s2[1] + s2[2] + s2[3];
    float mu  = s * (1.f / D_);
    float var = ss * (1.f / D_) - mu * mu;
    float rstd = rsqrtf(var + LN_EPS_);
    float4 g4 = ((const float4*)gam)[tid];
    float4 b4 = ((const float4*)bet)[tid];
    float4 o4;
    o4.x = (x4.x - mu) * rstd * g4.x + b4.x;
    o4.y = (x4.y - mu) * rstd * g4.y + b4.y;
    o4.z = (x4.z - mu) * rstd * g4.z + b4.z;
    o4.w = (x4.w - mu) * rstd * g4.w + b4.w;
    ((float4*)(out + (size_t)row * D_))[tid] = o4;
    if (out_r != nullptr)
        ((float4*)(out_r + (size_t)row * D_))[tid] =
            make_float4(rtf(o4.x), rtf(o4.y), rtf(o4.z), rtf(o4.w));
}

// ---------------- driver ----------------
extern "C" void kernel_launch(void* const* d_in, const int* in_sizes, int n_in,
                              void* d_out, int out_size) {
    const int*   x   = (const int*)  d_in[0];
    const float* emb = (const float*)d_in[1];
    const float* pe  = (const float*)d_in[2];
    const float* Wq  = (const float*)d_in[3];
    const float* bq  = (const float*)d_in[4];
    const float* Wk  = (const float*)d_in[5];
    const float* bk  = (const float*)d_in[6];
    const float* Wv  = (const float*)d_in[7];
    const float* bv  = (const float*)d_in[8];
    const float* Wo  = (const float*)d_in[9];
    const float* bo  = (const float*)d_in[10];
    const float* W1  = (const float*)d_in[11];
    const float* b1  = (const float*)d_in[12];
    const float* W2  = (const float*)d_in[13];
    const float* b2  = (const float*)d_in[14];
    const float* g1  = (const float*)d_in[15];
    const float* be1 = (const float*)d_in[16];
    const float* g2  = (const float*)d_in[17];
    const float* be2 = (const float*)d_in[18];
    const float* gf  = (const float*)d_in[19];
    const float* bf  = (const float*)d_in[20];
    float* out = (float*)d_out;

    float *p_h, *p_hr, *p_qkv, *p_attn, *p_tmp, *p_ffn, *p_wr;
    cudaGetSymbolAddress((void**)&p_h,    g_h);
    cudaGetSymbolAddress((void**)&p_hr,   g_hr);
    cudaGetSymbolAddress((void**)&p_qkv,  g_qkv);
    cudaGetSymbolAddress((void**)&p_attn, g_attn);
    cudaGetSymbolAddress((void**)&p_tmp,  g_tmp);
    cudaGetSymbolAddress((void**)&p_ffn,  g_ffn);
    cudaGetSymbolAddress((void**)&p_wr,   g_wr);

    cudaFuncSetAttribute(attn_out_kernel,
                         cudaFuncAttributeMaxDynamicSharedMemorySize, SM3_BYTES);
    cudaFuncSetAttribute(tgemm_kernel,
                         cudaFuncAttributeMaxDynamicSharedMemorySize, GSM_BYTES);

    lengths_kernel<<<B_, 256>>>(x);
    embed_kernel<<<BS_, 128>>>(x, emb, pe);
    pack_kernel<<<2048, 256>>>(Wq, Wk, Wv, Wo, W1, W2, bq, bk, bv);

    dim3 gQ(QS_ / 256, BS_ / 128);  // (6, 64)
    dim3 gD(D_ / 256, BS_ / 128);   // (2, 64)
    dim3 gF(F_ / 256, BS_ / 128);   // (8, 64)

    for (int l = 0; l < NL_; l++) {
        const float* wqkv = p_wr + (size_t)l * LWP_;
        const float* wo   = wqkv + R_QKV;
        const float* w1   = wo + R_WO;
        const float* w2   = w1 + R_W1;
        const float* bqkv = wqkv + LW_;
        const float* bo_l = bo + (size_t)l * D_;
        const float* b1_l = b1 + (size_t)l * F_;
        const float* b2_l = b2 + (size_t)l * D_;

        tgemm_kernel<<<gQ, 256, GSM_BYTES>>>(p_hr, wqkv, bqkv, p_qkv, BS_, QS_, D_, 0);

        attn_kv_kernel<<<BH * NC, 256>>>(p_qkv);
        attn_prefix_kernel<<<dim3(BH, 16), 256>>>();
        attn_out_kernel<<<BH * NC, 256, SM3_BYTES>>>(p_qkv, p_attn);

        tgemm_kernel<<<gD, 256, GSM_BYTES>>>(p_attn, wo, bo_l, p_tmp, BS_, D_, D_, 0);
        ln_kernel<<<BS_, 128>>>(p_h, p_tmp, g1 + (size_t)l * D_, be1 + (size_t)l * D_, p_h, p_hr);

        tgemm_kernel<<<gF, 256, GSM_BYTES>>>(p_hr, w1, b1_l, p_ffn, BS_, F_, D_, 1 | 2);
        tgemm_kernel<<<gD, 256, GSM_BYTES>>>(p_ffn, w2, b2_l, p_tmp, BS_, D_, F_, 0);
        ln_kernel<<<BS_, 128>>>(p_h, p_tmp, g2 + (size_t)l * D_, be2 + (size_t)l * D_, p_h, p_hr);
    }

    ln_kernel<<<BS_, 128>>>(p_h, nullptr, gf, bf, out, nullptr);
    (void)in_sizes; (void)n_in; (void)out_size;
}